// round 7
// baseline (speedup 1.0000x reference)
#include <cuda_runtime.h>
#include <cuda_bf16.h>
#include <math.h>
#include <stdint.h>

// Problem constants
#define B_  4
#define V_  256
#define H_  128
#define H2_ 64
#define L_  3
#define BV_ (B_*V_)              // 1024
#define XN_ (BV_*H_)             // 131072
#define EN_ 33554432             // B*V*V*H

// Scratch (allocation-free: __device__ globals)
// e stored SPLIT: hi/lo bf16 planes (hi+lo reconstructs ~fp32 precision)
__device__ __align__(16) __nv_bfloat16 d_ehi[EN_];
__device__ __align__(16) __nv_bfloat16 d_elo[EN_];
__device__ float d_etmp[EN_];
__device__ float d_xbuf[XN_];
__device__ float d_Vex[XN_];
__device__ float d_Vnx[XN_];
__device__ float d_Unx[XN_];
__device__ float d_xtmp[XN_];
// [0:128) e-ssum, [128:256) e-ssq, [256:384) x-sum, [384:512) x-sumsq
__device__ __align__(16) float d_stats[512];
// UeT (transposed Ue: row = output h, col = k) hi/lo bf16, plain [128][128]
__device__ __align__(16) __nv_bfloat16 d_UeThi[H_ * H_];
__device__ __align__(16) __nv_bfloat16 d_UeTlo[H_ * H_];

// ---- helpers --------------------------------------------------------------
__device__ __forceinline__ void split2(float a, float b, uint32_t& hi, uint32_t& lo) {
    __nv_bfloat162 h2;
    h2.x = __float2bfloat16_rn(a); h2.y = __float2bfloat16_rn(b);
    hi = *reinterpret_cast<uint32_t*>(&h2);
    __nv_bfloat162 l2;
    l2.x = __float2bfloat16_rn(a - __bfloat162float(h2.x));
    l2.y = __float2bfloat16_rn(b - __bfloat162float(h2.y));
    lo = *reinterpret_cast<uint32_t*>(&l2);
}
__device__ __forceinline__ float2 up_bf2(uint32_t u) {
    __nv_bfloat162 t = *reinterpret_cast<__nv_bfloat162*>(&u);
    return make_float2(__bfloat162float(t.x), __bfloat162float(t.y));
}
__device__ __forceinline__ uint32_t s2u(const void* p) {
    uint32_t a;
    asm("{ .reg .u64 t; cvta.to.shared.u64 t, %1; cvt.u32.u64 %0, t; }"
        : "=r"(a) : "l"(p));
    return a;
}
__device__ __forceinline__ void mma16816(float* d, const uint32_t* a,
                                         uint32_t b0, uint32_t b1) {
    asm volatile(
        "mma.sync.aligned.m16n8k16.row.col.f32.bf16.bf16.f32 "
        "{%0,%1,%2,%3}, {%4,%5,%6,%7}, {%8,%9}, {%0,%1,%2,%3};"
        : "+f"(d[0]), "+f"(d[1]), "+f"(d[2]), "+f"(d[3])
        : "r"(a[0]), "r"(a[1]), "r"(a[2]), "r"(a[3]), "r"(b0), "r"(b1));
}
__device__ __forceinline__ void ldsm4(uint32_t addr, uint32_t* r) {
    asm volatile("ldmatrix.sync.aligned.m8n8.x4.shared.b16 {%0,%1,%2,%3}, [%4];"
        : "=r"(r[0]), "=r"(r[1]), "=r"(r[2]), "=r"(r[3]) : "r"(addr));
}
#define CP16(dst, src) \
    asm volatile("cp.async.cg.shared.global [%0], [%1], 16;" :: "r"(dst), "l"(src))
#define CPCOMMIT() asm volatile("cp.async.commit_group;")

// ---------------------------------------------------------------------------
// x = coord @ W_node + b_node
__global__ void node_embed_kernel(const float* __restrict__ coord,
                                  const float* __restrict__ Wn,
                                  const float* __restrict__ bn) {
    int idx = blockIdx.x * blockDim.x + threadIdx.x;
    int h = idx & (H_ - 1);
    int row = idx >> 7;
    const float* c = coord + row * 3;
    d_xbuf[idx] = c[0] * Wn[h] + c[1] * Wn[H_ + h] + c[2] * Wn[2 * H_ + h] + bn[h];
}

// e = concat(ev*Wev + bev, tour*Wec0 + best*Wec1 + bec), written SPLIT
__global__ void edge_embed_kernel(const float* __restrict__ ev,
                                  const float* __restrict__ tour,
                                  const float* __restrict__ btour,
                                  const float* __restrict__ Wev,
                                  const float* __restrict__ bev,
                                  const float* __restrict__ Wec,
                                  const float* __restrict__ bec) {
    int idx4 = blockIdx.x * blockDim.x + threadIdx.x;  // EN_/4
    int h4 = idx4 & 31;
    int edge = idx4 >> 5;
    int h0 = h4 * 4;
    float4 o;
    if (h0 < H2_) {
        float v = ev[edge];
        o.x = v * Wev[h0 + 0] + bev[h0 + 0];
        o.y = v * Wev[h0 + 1] + bev[h0 + 1];
        o.z = v * Wev[h0 + 2] + bev[h0 + 2];
        o.w = v * Wev[h0 + 3] + bev[h0 + 3];
    } else {
        float t = tour[edge], bt = btour[edge];
        int g = h0 - H2_;
        o.x = t * Wec[g + 0] + bt * Wec[H2_ + g + 0] + bec[g + 0];
        o.y = t * Wec[g + 1] + bt * Wec[H2_ + g + 1] + bec[g + 1];
        o.z = t * Wec[g + 2] + bt * Wec[H2_ + g + 2] + bec[g + 2];
        o.w = t * Wec[g + 3] + bt * Wec[H2_ + g + 3] + bec[g + 3];
    }
    uint2 hi, lo;
    split2(o.x, o.y, hi.x, lo.x);
    split2(o.z, o.w, hi.y, lo.y);
    reinterpret_cast<uint2*>(d_ehi)[idx4] = hi;
    reinterpret_cast<uint2*>(d_elo)[idx4] = lo;
}

// Combined per-layer prep: blocks 0-63 = Vex/Vnx/Unx gemm3; 64-191 = UeT split;
// block 192 = zero stats.
__global__ void __launch_bounds__(128) prep_kernel(
        const float* __restrict__ Ue,
        const float* __restrict__ Ve, const float* __restrict__ bVe,
        const float* __restrict__ Vn, const float* __restrict__ bVn,
        const float* __restrict__ Un, const float* __restrict__ bUn) {
    int bid = blockIdx.x;
    int tid = threadIdx.x;
    if (bid >= 192) {
        for (int i = tid; i < 512; i += 128) d_stats[i] = 0.f;
        return;
    }
    if (bid >= 64) {
        int h = bid - 64;
        int k = tid;
        float f = Ue[k * H_ + h];
        __nv_bfloat16 hi = __float2bfloat16_rn(f);
        d_UeThi[h * H_ + k] = hi;
        d_UeTlo[h * H_ + k] = __float2bfloat16_rn(f - __bfloat162float(hi));
        return;
    }
    __shared__ float xs[16 * H_];
    int h = tid;
    int r0 = bid * 16;
    {
        const float4* src = reinterpret_cast<const float4*>(d_xbuf + r0 * H_);
        float4* dst = reinterpret_cast<float4*>(xs);
#pragma unroll
        for (int t = 0; t < 4; ++t) dst[h + t * 128] = src[h + t * 128];
    }
    __syncthreads();
    float a0[16], a1[16], a2[16];
    {
        float v0 = bVe[h], v1 = bVn[h], v2 = bUn[h];
#pragma unroll
        for (int r = 0; r < 16; ++r) { a0[r] = v0; a1[r] = v1; a2[r] = v2; }
    }
    for (int k = 0; k < H_; k += 4) {
        float w0[4], w1[4], w2[4];
#pragma unroll
        for (int q = 0; q < 4; ++q) {
            w0[q] = Ve[(k + q) * H_ + h];
            w1[q] = Vn[(k + q) * H_ + h];
            w2[q] = Un[(k + q) * H_ + h];
        }
#pragma unroll
        for (int r = 0; r < 16; ++r) {
            float4 xv = *reinterpret_cast<const float4*>(xs + r * H_ + k);
            a0[r] += xv.x * w0[0] + xv.y * w0[1] + xv.z * w0[2] + xv.w * w0[3];
            a1[r] += xv.x * w1[0] + xv.y * w1[1] + xv.z * w1[2] + xv.w * w1[3];
            a2[r] += xv.x * w2[0] + xv.y * w2[1] + xv.z * w2[2] + xv.w * w2[3];
        }
    }
#pragma unroll
    for (int r = 0; r < 16; ++r) {
        d_Vex[(r0 + r) * H_ + h] = a0[r];
        d_Vnx[(r0 + r) * H_ + h] = a1[r];
        d_Unx[(r0 + r) * H_ + h] = a2[r];
    }
}

// ---------------------------------------------------------------------------
// Fused edge layer: 64-j slabs (single-buffered; next-slab cp.async overlaps
// epilogue), warp tile 32j x 32h (2 m-tiles x 4 n-tiles), ldmatrix + mma.sync,
// 3-term bf16 hi/lo split. Smem XOR-swizzled 256B rows.
#define OFF_UHI  0          // 32768
#define OFF_ULO  32768      // 32768
#define OFF_E    65536      // hi 16384, lo @81920 (64 rows x 256B each)
#define OFF_BASE 98304      // 512
#define OFF_RED  98816      // 4096
#define SMEM_F   102912

__device__ __forceinline__ void fetch_slab(uint32_t smb, size_t erow_elem,
                                           int s, int tid) {
    // 2048 x 16B chunks: 2 planes x 64 rows x 16 chunks
#pragma unroll
    for (int t = 0; t < 8; ++t) {
        int idx = tid + t * 256;
        int plane = idx >> 10;
        int r = (idx >> 4) & 63;
        int c = idx & 15;
        const __nv_bfloat16* src =
            (plane ? d_elo : d_ehi) + erow_elem + (size_t)(s * 64 + r) * H_ + c * 8;
        uint32_t dst = smb + OFF_E + plane * 16384 + r * 256 + ((c ^ (r & 7)) << 4);
        CP16(dst, src);
    }
}

__global__ void __launch_bounds__(256, 2) fused_edge_kernel(
        const float* __restrict__ bUe, int write_e) {
    extern __shared__ char smc[];
    uint32_t smb = s2u(smc);
    int tid = threadIdx.x, w = tid >> 5, lane = tid & 31;
    int wj = w & 1, wh = w >> 1;
    int bi = blockIdx.x, b = bi >> 8;
    size_t erow = (size_t)bi * (V_ * H_);

    // prologue: U tiles (4096 chunks) + e slab 0
#pragma unroll
    for (int t = 0; t < 16; ++t) {
        int idx = tid + t * 256;
        int plane = idx >> 11;
        int hrow = (idx >> 4) & 127;
        int c = idx & 15;
        const __nv_bfloat16* src =
            (plane ? d_UeTlo : d_UeThi) + hrow * H_ + c * 8;
        uint32_t dst = smb + (plane ? OFF_ULO : OFF_UHI) +
                       hrow * 256 + ((c ^ (hrow & 7)) << 4);
        CP16(dst, src);
    }
    fetch_slab(smb, erow, 0, tid);
    CPCOMMIT();
    if (tid < H_)
        reinterpret_cast<float*>(smc + OFF_BASE)[tid] =
            bUe[tid] + d_Vex[bi * H_ + tid];

    const float* VexB = d_Vex + (size_t)b * V_ * H_;
    const float* VnxB = d_Vnx + (size_t)b * V_ * H_;
    float* etrow = d_etmp + erow;

    // fragment addressing
    int ra = wj * 32 + (lane & 15);
    uint32_t aB0 = smb + OFF_E + ra * 256;            // m=0 (hi); +16384 lo
    uint32_t aB1 = aB0 + 16 * 256;                    // m=1
    int am = ra & 7;                                  // (ra+16)&7 == am
    int ach = lane >> 4;
    int rb = wh * 32 + ((lane >> 4) & 1) * 8 + (lane & 7);
    uint32_t bB0 = smb + OFF_UHI + rb * 256;          // p=0; +32768 lo
    uint32_t bB1 = bB0 + 16 * 256;                    // p=1
    int bm = rb & 7;
    int bch = (lane >> 3) & 1;

    float sN0[4], sN1[4], sD0[4], sD1[4], sS0[4], sS1[4], sQ0[4], sQ1[4];
#pragma unroll
    for (int n = 0; n < 4; ++n) {
        sN0[n] = sN1[n] = sD0[n] = sD1[n] = 0.f;
        sS0[n] = sS1[n] = sQ0[n] = sQ1[n] = 0.f;
    }

    for (int s = 0; s < 4; ++s) {
        asm volatile("cp.async.wait_group 0;");
        __syncthreads();

        float acc[2][4][4];
#pragma unroll
        for (int m = 0; m < 2; ++m)
#pragma unroll
            for (int n = 0; n < 4; ++n)
#pragma unroll
                for (int q = 0; q < 4; ++q) acc[m][n][q] = 0.f;

#pragma unroll
        for (int kk = 0; kk < 8; ++kk) {
            uint32_t ah0[4], ah1[4], al0[4], al1[4];
            uint32_t ao = (uint32_t)(((kk * 2 + ach) ^ am) << 4);
            ldsm4(aB0 + ao, ah0);
            ldsm4(aB1 + ao, ah1);
            ldsm4(aB0 + 16384 + ao, al0);
            ldsm4(aB1 + 16384 + ao, al1);
#pragma unroll
            for (int p = 0; p < 2; ++p) {
                uint32_t bh[4], bl[4];
                uint32_t bo = (uint32_t)(((kk * 2 + bch) ^ bm) << 4);
                uint32_t bb = p ? bB1 : bB0;
                ldsm4(bb + bo, bh);
                ldsm4(bb + 32768 + bo, bl);
                mma16816(acc[0][p * 2],     ah0, bh[0], bh[1]);
                mma16816(acc[0][p * 2],     al0, bh[0], bh[1]);
                mma16816(acc[0][p * 2],     ah0, bl[0], bl[1]);
                mma16816(acc[0][p * 2 + 1], ah0, bh[2], bh[3]);
                mma16816(acc[0][p * 2 + 1], al0, bh[2], bh[3]);
                mma16816(acc[0][p * 2 + 1], ah0, bl[2], bl[3]);
                mma16816(acc[1][p * 2],     ah1, bh[0], bh[1]);
                mma16816(acc[1][p * 2],     al1, bh[0], bh[1]);
                mma16816(acc[1][p * 2],     ah1, bl[0], bl[1]);
                mma16816(acc[1][p * 2 + 1], ah1, bh[2], bh[3]);
                mma16816(acc[1][p * 2 + 1], al1, bh[2], bh[3]);
                mma16816(acc[1][p * 2 + 1], ah1, bl[2], bl[3]);
            }
        }

        __syncthreads();                      // all warps done reading E smem
        if (s < 3) { fetch_slab(smb, erow, s + 1, tid); CPCOMMIT(); }

        // epilogue overlaps the async fetch
#pragma unroll
        for (int n = 0; n < 4; ++n) {
            int h0 = wh * 32 + n * 8 + (lane & 3) * 2;
            float2 bse = *reinterpret_cast<const float2*>(smc + OFF_BASE + h0 * 4);
#pragma unroll
            for (int m = 0; m < 2; ++m) {
                int jr0 = s * 64 + wj * 32 + m * 16 + (lane >> 2);
                int jr1 = jr0 + 8;
                float2 vx0 = *reinterpret_cast<const float2*>(VexB + jr0 * H_ + h0);
                float2 vx1 = *reinterpret_cast<const float2*>(VexB + jr1 * H_ + h0);
                float2 vn0 = *reinterpret_cast<const float2*>(VnxB + jr0 * H_ + h0);
                float2 vn1 = *reinterpret_cast<const float2*>(VnxB + jr1 * H_ + h0);
                float et00 = acc[m][n][0] + bse.x + vx0.x;
                float et01 = acc[m][n][1] + bse.y + vx0.y;
                float et10 = acc[m][n][2] + bse.x + vx1.x;
                float et11 = acc[m][n][3] + bse.y + vx1.y;
                float g00 = 1.f / (1.f + __expf(-et00));
                float g01 = 1.f / (1.f + __expf(-et01));
                float g10 = 1.f / (1.f + __expf(-et10));
                float g11 = 1.f / (1.f + __expf(-et11));
                sN0[n] += g00 * vn0.x + g10 * vn1.x;
                sN1[n] += g01 * vn0.y + g11 * vn1.y;
                sD0[n] += g00 + g10;
                sD1[n] += g01 + g11;
                if (write_e) {
                    sS0[n] += et00 + et10;
                    sS1[n] += et01 + et11;
                    sQ0[n] += et00 * et00 + et10 * et10;
                    sQ1[n] += et01 * et01 + et11 * et11;
                    *reinterpret_cast<float2*>(etrow + (size_t)jr0 * H_ + h0) =
                        make_float2(et00, et01);
                    *reinterpret_cast<float2*>(etrow + (size_t)jr1 * H_ + h0) =
                        make_float2(et10, et11);
                }
            }
        }
    }

    // final reduction over j-lanes (xor shuffles), then smem across wj groups
    float* red = reinterpret_cast<float*>(smc + OFF_RED);
#pragma unroll
    for (int n = 0; n < 4; ++n) {
#pragma unroll
        for (int o = 4; o < 32; o <<= 1) {
            sN0[n] += __shfl_xor_sync(0xffffffffu, sN0[n], o);
            sN1[n] += __shfl_xor_sync(0xffffffffu, sN1[n], o);
            sD0[n] += __shfl_xor_sync(0xffffffffu, sD0[n], o);
            sD1[n] += __shfl_xor_sync(0xffffffffu, sD1[n], o);
        }
        if (write_e) {
#pragma unroll
            for (int o = 4; o < 32; o <<= 1) {
                sS0[n] += __shfl_xor_sync(0xffffffffu, sS0[n], o);
                sS1[n] += __shfl_xor_sync(0xffffffffu, sS1[n], o);
                sQ0[n] += __shfl_xor_sync(0xffffffffu, sQ0[n], o);
                sQ1[n] += __shfl_xor_sync(0xffffffffu, sQ1[n], o);
            }
        }
        if (lane < 4) {
            int h = wh * 32 + n * 8 + lane * 2;
            red[(0 * 2 + wj) * 128 + h]     = sN0[n];
            red[(0 * 2 + wj) * 128 + h + 1] = sN1[n];
            red[(1 * 2 + wj) * 128 + h]     = sD0[n];
            red[(1 * 2 + wj) * 128 + h + 1] = sD1[n];
            red[(2 * 2 + wj) * 128 + h]     = sS0[n];
            red[(2 * 2 + wj) * 128 + h + 1] = sS1[n];
            red[(3 * 2 + wj) * 128 + h]     = sQ0[n];
            red[(3 * 2 + wj) * 128 + h + 1] = sQ1[n];
        }
    }
    __syncthreads();
    if (tid < H_) {
        float n = red[tid] + red[128 + tid];
        float d = red[256 + tid] + red[384 + tid];
        float aggv = n / (d + 1e-20f);
        float xt = aggv + d_Unx[bi * H_ + tid];
        d_xtmp[bi * H_ + tid] = xt;
        atomicAdd(&d_stats[256 + tid], xt);
        atomicAdd(&d_stats[384 + tid], xt * xt);
        if (write_e) {
            atomicAdd(&d_stats[tid],       red[512 + tid] + red[640 + tid]);
            atomicAdd(&d_stats[128 + tid], red[768 + tid] + red[896 + tid]);
        }
    }
}

// ---------------------------------------------------------------------------
// Merged update: blocks [0,512) x += relu(bn(x_tmp)); blocks [512,...) e-update
// with scale/shift recomputed inline from the global stats.
__global__ void update_kernel(const float* __restrict__ gx,
                              const float* __restrict__ bx,
                              const float* __restrict__ ge,
                              const float* __restrict__ be) {
    int bid = blockIdx.x;
    int tid = threadIdx.x;
    if (bid < 512) {
        int idx = bid * 256 + tid;            // XN_
        int h = idx & (H_ - 1);
        const float inv = 1.f / (float)BV_;
        float mu  = d_stats[256 + h] * inv;
        float var = d_stats[384 + h] * inv - mu * mu;
        float t = gx[h] * (d_xtmp[idx] - mu) * rsqrtf(var + 1e-5f) + bx[h];
        d_xbuf[idx] += fmaxf(t, 0.f);
        return;
    }
    int idx4 = (bid - 512) * 256 + tid;       // EN_/4
    int h0 = (idx4 & 31) * 4;
    const float inv = 1.f / (float)(B_ * V_ * V_);
    float4 s1 = *reinterpret_cast<const float4*>(d_stats + h0);
    float4 s2 = *reinterpret_cast<const float4*>(d_stats + 128 + h0);
    float4 g4 = *reinterpret_cast<const float4*>(ge + h0);
    float4 b4 = *reinterpret_cast<const float4*>(be + h0);
    float mux = s1.x * inv, muy = s1.y * inv, muz = s1.z * inv, muw = s1.w * inv;
    float scx = g4.x * rsqrtf(s2.x * inv - mux * mux + 1e-5f);
    float scy = g4.y * rsqrtf(s2.y * inv - muy * muy + 1e-5f);
    float scz = g4.z * rsqrtf(s2.z * inv - muz * muz + 1e-5f);
    float scw = g4.w * rsqrtf(s2.w * inv - muw * muw + 1e-5f);
    float shx = b4.x - mux * scx, shy = b4.y - muy * scy;
    float shz = b4.z - muz * scz, shw = b4.w - muw * scw;
    uint2 hi = reinterpret_cast<const uint2*>(d_ehi)[idx4];
    uint2 lo = reinterpret_cast<const uint2*>(d_elo)[idx4];
    float4 et = reinterpret_cast<const float4*>(d_etmp)[idx4];
    float2 hxy = up_bf2(hi.x), hzw = up_bf2(hi.y);
    float2 lxy = up_bf2(lo.x), lzw = up_bf2(lo.y);
    float vx = hxy.x + lxy.x + fmaxf(et.x * scx + shx, 0.f);
    float vy = hxy.y + lxy.y + fmaxf(et.y * scy + shy, 0.f);
    float vz = hzw.x + lzw.x + fmaxf(et.z * scz + shz, 0.f);
    float vw = hzw.y + lzw.y + fmaxf(et.w * scw + shw, 0.f);
    uint2 nhi, nlo;
    split2(vx, vy, nhi.x, nlo.x);
    split2(vz, vw, nhi.y, nlo.y);
    reinterpret_cast<uint2*>(d_ehi)[idx4] = nhi;
    reinterpret_cast<uint2*>(d_elo)[idx4] = nlo;
}

__global__ void zero_out_kernel(float* out) {
    if (threadIdx.x < B_) out[threadIdx.x] = 0.f;
}

// per (b,v): h = relu(x@W1+b1); v = h@W2 + b2; out[b] += v/V
__global__ void readout_kernel(const float* __restrict__ W1,
                               const float* __restrict__ b1,
                               const float* __restrict__ W2,
                               const float* __restrict__ b2,
                               float* __restrict__ out) {
    __shared__ float xs[H_];
    __shared__ float wred[4];
    int row = blockIdx.x;
    int tid = threadIdx.x;
    xs[tid] = d_xbuf[row * H_ + tid];
    __syncthreads();
    float acc = b1[tid];
#pragma unroll 8
    for (int k = 0; k < H_; ++k) acc += xs[k] * W1[k * H_ + tid];
    float v = fmaxf(acc, 0.f) * W2[tid];
#pragma unroll
    for (int o = 16; o > 0; o >>= 1) v += __shfl_down_sync(0xffffffffu, v, o);
    if ((tid & 31) == 0) wred[tid >> 5] = v;
    __syncthreads();
    if (tid == 0) {
        float s = wred[0] + wred[1] + wred[2] + wred[3] + b2[0];
        atomicAdd(&out[row >> 8], s * (1.f / (float)V_));
    }
}

// ---------------------------------------------------------------------------
extern "C" void kernel_launch(void* const* d_in, const int* in_sizes, int n_in,
                              void* d_out, int out_size) {
    const float* xev   = (const float*)d_in[1];
    const float* coord = (const float*)d_in[2];
    const float* tour  = (const float*)d_in[3];
    const float* btour = (const float*)d_in[4];
    const float* Wn    = (const float*)d_in[5];
    const float* bn    = (const float*)d_in[6];
    const float* Wev   = (const float*)d_in[7];
    const float* bev   = (const float*)d_in[8];
    const float* Wec   = (const float*)d_in[9];
    const float* bec   = (const float*)d_in[10];
    const float* Ue    = (const float*)d_in[11];
    const float* bUe   = (const float*)d_in[12];
    const float* Ve    = (const float*)d_in[13];
    const float* bVe   = (const float*)d_in[14];
    const float* Un    = (const float*)d_in[15];
    const float* bUn   = (const float*)d_in[16];
    const float* Vn    = (const float*)d_in[17];
    const float* bVn   = (const float*)d_in[18];
    const float* ge    = (const float*)d_in[19];
    const float* be    = (const float*)d_in[20];
    const float* gx    = (const float*)d_in[21];
    const float* bx    = (const float*)d_in[22];
    const float* W1    = (const float*)d_in[23];
    const float* b1    = (const float*)d_in[24];
    const float* W2    = (const float*)d_in[25];
    const float* b2    = (const float*)d_in[26];
    float* out = (float*)d_out;

    cudaFuncSetAttribute(fused_edge_kernel,
                         cudaFuncAttributeMaxDynamicSharedMemorySize, SMEM_F);

    node_embed_kernel<<<XN_ / 256, 256>>>(coord, Wn, bn);
    edge_embed_kernel<<<EN_ / 4 / 256, 256>>>(xev, tour, btour, Wev, bev, Wec, bec);

    for (int l = 0; l < L_; ++l) {
        prep_kernel<<<193, 128>>>(Ue + l * H_ * H_,
                                  Ve + l * H_ * H_, bVe + l * H_,
                                  Vn + l * H_ * H_, bVn + l * H_,
                                  Un + l * H_ * H_, bUn + l * H_);
        int write_e = (l < L_ - 1) ? 1 : 0;
        fused_edge_kernel<<<BV_, 256, SMEM_F>>>(bUe + l * H_, write_e);
        int nblk = 512 + (write_e ? (EN_ / 4 / 256) : 0);
        update_kernel<<<nblk, 256>>>(gx + l * H_, bx + l * H_,
                                     ge + l * H_, be + l * H_);
    }

    zero_out_kernel<<<1, 32>>>(out);
    readout_kernel<<<BV_, H_>>>(W1, b1, W2, b2, out);
}

// round 8
// speedup vs baseline: 1.0536x; 1.0536x over previous
#include <cuda_runtime.h>
#include <cuda_fp16.h>
#include <math.h>
#include <stdint.h>

// Problem constants
#define B_  4
#define V_  256
#define H_  128
#define H2_ 64
#define L_  3
#define BV_ (B_*V_)              // 1024
#define XN_ (BV_*H_)             // 131072
#define EN_ 33554432             // B*V*V*H

// Scratch (allocation-free: __device__ globals)
// e stored SPLIT: hi/lo fp16 planes (hi+lo ~ 22-bit mantissa)
__device__ __align__(16) __half d_ehi[EN_];
__device__ __align__(16) __half d_elo[EN_];
__device__ float d_etmp[EN_];
__device__ float d_xbuf[XN_];
__device__ float d_Vex[XN_];
__device__ float d_Vnx[XN_];
__device__ float d_Unx[XN_];
__device__ float d_xtmp[XN_];
// [0:128) e-ssum, [128:256) e-ssq, [256:384) x-sum, [384:512) x-sumsq
__device__ __align__(16) float d_stats[512];
// UeT (transposed Ue: row = output h, col = k), single fp16 plane [128][128]
__device__ __align__(16) __half d_UeTh[H_ * H_];

// ---- helpers --------------------------------------------------------------
__device__ __forceinline__ void split2h(float a, float b, uint32_t& hi, uint32_t& lo) {
    __half2 h2;
    h2.x = __float2half_rn(a); h2.y = __float2half_rn(b);
    hi = *reinterpret_cast<uint32_t*>(&h2);
    __half2 l2;
    l2.x = __float2half_rn(a - __half2float(h2.x));
    l2.y = __float2half_rn(b - __half2float(h2.y));
    lo = *reinterpret_cast<uint32_t*>(&l2);
}
__device__ __forceinline__ float2 up_h2(uint32_t u) {
    __half2 t = *reinterpret_cast<__half2*>(&u);
    return make_float2(__half2float(t.x), __half2float(t.y));
}
__device__ __forceinline__ uint32_t s2u(const void* p) {
    uint32_t a;
    asm("{ .reg .u64 t; cvta.to.shared.u64 t, %1; cvt.u32.u64 %0, t; }"
        : "=r"(a) : "l"(p));
    return a;
}
__device__ __forceinline__ void mma16816h(float* d, const uint32_t* a,
                                          uint32_t b0, uint32_t b1) {
    asm volatile(
        "mma.sync.aligned.m16n8k16.row.col.f32.f16.f16.f32 "
        "{%0,%1,%2,%3}, {%4,%5,%6,%7}, {%8,%9}, {%0,%1,%2,%3};"
        : "+f"(d[0]), "+f"(d[1]), "+f"(d[2]), "+f"(d[3])
        : "r"(a[0]), "r"(a[1]), "r"(a[2]), "r"(a[3]), "r"(b0), "r"(b1));
}
__device__ __forceinline__ void ldsm4(uint32_t addr, uint32_t* r) {
    asm volatile("ldmatrix.sync.aligned.m8n8.x4.shared.b16 {%0,%1,%2,%3}, [%4];"
        : "=r"(r[0]), "=r"(r[1]), "=r"(r[2]), "=r"(r[3]) : "r"(addr));
}
#define CP16(dst, src) \
    asm volatile("cp.async.cg.shared.global [%0], [%1], 16;" :: "r"(dst), "l"(src))
#define CPCOMMIT() asm volatile("cp.async.commit_group;")

// ---------------------------------------------------------------------------
// x = coord @ W_node + b_node
__global__ void node_embed_kernel(const float* __restrict__ coord,
                                  const float* __restrict__ Wn,
                                  const float* __restrict__ bn) {
    int idx = blockIdx.x * blockDim.x + threadIdx.x;
    int h = idx & (H_ - 1);
    int row = idx >> 7;
    const float* c = coord + row * 3;
    d_xbuf[idx] = c[0] * Wn[h] + c[1] * Wn[H_ + h] + c[2] * Wn[2 * H_ + h] + bn[h];
}

// e = concat(ev*Wev + bev, tour*Wec0 + best*Wec1 + bec), written SPLIT fp16
__global__ void edge_embed_kernel(const float* __restrict__ ev,
                                  const float* __restrict__ tour,
                                  const float* __restrict__ btour,
                                  const float* __restrict__ Wev,
                                  const float* __restrict__ bev,
                                  const float* __restrict__ Wec,
                                  const float* __restrict__ bec) {
    int idx4 = blockIdx.x * blockDim.x + threadIdx.x;  // EN_/4
    int h4 = idx4 & 31;
    int edge = idx4 >> 5;
    int h0 = h4 * 4;
    float4 o;
    if (h0 < H2_) {
        float v = ev[edge];
        o.x = v * Wev[h0 + 0] + bev[h0 + 0];
        o.y = v * Wev[h0 + 1] + bev[h0 + 1];
        o.z = v * Wev[h0 + 2] + bev[h0 + 2];
        o.w = v * Wev[h0 + 3] + bev[h0 + 3];
    } else {
        float t = tour[edge], bt = btour[edge];
        int g = h0 - H2_;
        o.x = t * Wec[g + 0] + bt * Wec[H2_ + g + 0] + bec[g + 0];
        o.y = t * Wec[g + 1] + bt * Wec[H2_ + g + 1] + bec[g + 1];
        o.z = t * Wec[g + 2] + bt * Wec[H2_ + g + 2] + bec[g + 2];
        o.w = t * Wec[g + 3] + bt * Wec[H2_ + g + 3] + bec[g + 3];
    }
    uint2 hi, lo;
    split2h(o.x, o.y, hi.x, lo.x);
    split2h(o.z, o.w, hi.y, lo.y);
    reinterpret_cast<uint2*>(d_ehi)[idx4] = hi;
    reinterpret_cast<uint2*>(d_elo)[idx4] = lo;
}

// Combined per-layer prep: blocks 0-63 = Vex/Vnx/Unx gemm3; 64-191 = UeT fp16;
// block 192 = zero stats.
__global__ void __launch_bounds__(128) prep_kernel(
        const float* __restrict__ Ue,
        const float* __restrict__ Ve, const float* __restrict__ bVe,
        const float* __restrict__ Vn, const float* __restrict__ bVn,
        const float* __restrict__ Un, const float* __restrict__ bUn) {
    int bid = blockIdx.x;
    int tid = threadIdx.x;
    if (bid >= 192) {
        for (int i = tid; i < 512; i += 128) d_stats[i] = 0.f;
        return;
    }
    if (bid >= 64) {
        int h = bid - 64;
        int k = tid;
        d_UeTh[h * H_ + k] = __float2half_rn(Ue[k * H_ + h]);
        return;
    }
    __shared__ float xs[16 * H_];
    int h = tid;
    int r0 = bid * 16;
    {
        const float4* src = reinterpret_cast<const float4*>(d_xbuf + r0 * H_);
        float4* dst = reinterpret_cast<float4*>(xs);
#pragma unroll
        for (int t = 0; t < 4; ++t) dst[h + t * 128] = src[h + t * 128];
    }
    __syncthreads();
    float a0[16], a1[16], a2[16];
    {
        float v0 = bVe[h], v1 = bVn[h], v2 = bUn[h];
#pragma unroll
        for (int r = 0; r < 16; ++r) { a0[r] = v0; a1[r] = v1; a2[r] = v2; }
    }
    for (int k = 0; k < H_; k += 4) {
        float w0[4], w1[4], w2[4];
#pragma unroll
        for (int q = 0; q < 4; ++q) {
            w0[q] = Ve[(k + q) * H_ + h];
            w1[q] = Vn[(k + q) * H_ + h];
            w2[q] = Un[(k + q) * H_ + h];
        }
#pragma unroll
        for (int r = 0; r < 16; ++r) {
            float4 xv = *reinterpret_cast<const float4*>(xs + r * H_ + k);
            a0[r] += xv.x * w0[0] + xv.y * w0[1] + xv.z * w0[2] + xv.w * w0[3];
            a1[r] += xv.x * w1[0] + xv.y * w1[1] + xv.z * w1[2] + xv.w * w1[3];
            a2[r] += xv.x * w2[0] + xv.y * w2[1] + xv.z * w2[2] + xv.w * w2[3];
        }
    }
#pragma unroll
    for (int r = 0; r < 16; ++r) {
        d_Vex[(r0 + r) * H_ + h] = a0[r];
        d_Vnx[(r0 + r) * H_ + h] = a1[r];
        d_Unx[(r0 + r) * H_ + h] = a2[r];
    }
}

// ---------------------------------------------------------------------------
// Fused edge layer: fp16 2-term split (Ehi*U + Elo*U), 64-j slabs, warp tile
// 32j x 32h, ldmatrix + mma.sync, 3 CTAs/SM. Smem XOR-swizzled 256B rows.
#define OFF_UH   0          // 32768 (128 rows x 256B, single fp16 plane)
#define OFF_E    32768      // hi 16384 @32768, lo 16384 @49152
#define OFF_BASE 65536      // 512
#define OFF_RED  66048      // 4096
#define SMEM_F   70144

__device__ __forceinline__ void fetch_slab(uint32_t smb, size_t erow_elem,
                                           int s, int tid) {
    // 2048 x 16B chunks: 2 planes x 64 rows x 16 chunks
#pragma unroll
    for (int t = 0; t < 8; ++t) {
        int idx = tid + t * 256;
        int plane = idx >> 10;
        int r = (idx >> 4) & 63;
        int c = idx & 15;
        const __half* src =
            (plane ? d_elo : d_ehi) + erow_elem + (size_t)(s * 64 + r) * H_ + c * 8;
        uint32_t dst = smb + OFF_E + plane * 16384 + r * 256 + ((c ^ (r & 7)) << 4);
        CP16(dst, src);
    }
}

__global__ void __launch_bounds__(256, 3) fused_edge_kernel(
        const float* __restrict__ bUe, int write_e) {
    extern __shared__ char smc[];
    uint32_t smb = s2u(smc);
    int tid = threadIdx.x, w = tid >> 5, lane = tid & 31;
    int wj = w & 1, wh = w >> 1;
    int bi = blockIdx.x, b = bi >> 8;
    size_t erow = (size_t)bi * (V_ * H_);

    // prologue: U tile (2048 chunks) + e slab 0
#pragma unroll
    for (int t = 0; t < 8; ++t) {
        int idx = tid + t * 256;
        int hrow = idx >> 4;
        int c = idx & 15;
        const __half* src = d_UeTh + hrow * H_ + c * 8;
        uint32_t dst = smb + OFF_UH + hrow * 256 + ((c ^ (hrow & 7)) << 4);
        CP16(dst, src);
    }
    fetch_slab(smb, erow, 0, tid);
    CPCOMMIT();
    if (tid < H_)
        reinterpret_cast<float*>(smc + OFF_BASE)[tid] =
            bUe[tid] + d_Vex[bi * H_ + tid];

    const float* VexB = d_Vex + (size_t)b * V_ * H_;
    const float* VnxB = d_Vnx + (size_t)b * V_ * H_;
    float* etrow = d_etmp + erow;

    // fragment addressing
    int ra = wj * 32 + (lane & 15);
    uint32_t aB0 = smb + OFF_E + ra * 256;            // m=0 (hi); +16384 lo
    uint32_t aB1 = aB0 + 16 * 256;                    // m=1
    int am = ra & 7;
    int ach = lane >> 4;
    int rb = wh * 32 + ((lane >> 4) & 1) * 8 + (lane & 7);
    uint32_t bB0 = smb + OFF_UH + rb * 256;           // p=0
    uint32_t bB1 = bB0 + 16 * 256;                    // p=1
    int bm = rb & 7;
    int bch = (lane >> 3) & 1;

    float sN0[4], sN1[4], sD0[4], sD1[4], sS0[4], sS1[4], sQ0[4], sQ1[4];
#pragma unroll
    for (int n = 0; n < 4; ++n) {
        sN0[n] = sN1[n] = sD0[n] = sD1[n] = 0.f;
        sS0[n] = sS1[n] = sQ0[n] = sQ1[n] = 0.f;
    }

    for (int s = 0; s < 4; ++s) {
        asm volatile("cp.async.wait_group 0;");
        __syncthreads();

        float acc[2][4][4];
#pragma unroll
        for (int m = 0; m < 2; ++m)
#pragma unroll
            for (int n = 0; n < 4; ++n)
#pragma unroll
                for (int q = 0; q < 4; ++q) acc[m][n][q] = 0.f;

#pragma unroll
        for (int kk = 0; kk < 8; ++kk) {
            uint32_t ah0[4], ah1[4], al0[4], al1[4];
            uint32_t ao = (uint32_t)(((kk * 2 + ach) ^ am) << 4);
            ldsm4(aB0 + ao, ah0);
            ldsm4(aB1 + ao, ah1);
            ldsm4(aB0 + 16384 + ao, al0);
            ldsm4(aB1 + 16384 + ao, al1);
            uint32_t bh0[4], bh1[4];
            uint32_t bo = (uint32_t)(((kk * 2 + bch) ^ bm) << 4);
            ldsm4(bB0 + bo, bh0);
            ldsm4(bB1 + bo, bh1);
            // term-major order: each accumulator reused 8 MMAs apart
            mma16816h(acc[0][0], ah0, bh0[0], bh0[1]);
            mma16816h(acc[0][1], ah0, bh0[2], bh0[3]);
            mma16816h(acc[0][2], ah0, bh1[0], bh1[1]);
            mma16816h(acc[0][3], ah0, bh1[2], bh1[3]);
            mma16816h(acc[1][0], ah1, bh0[0], bh0[1]);
            mma16816h(acc[1][1], ah1, bh0[2], bh0[3]);
            mma16816h(acc[1][2], ah1, bh1[0], bh1[1]);
            mma16816h(acc[1][3], ah1, bh1[2], bh1[3]);
            mma16816h(acc[0][0], al0, bh0[0], bh0[1]);
            mma16816h(acc[0][1], al0, bh0[2], bh0[3]);
            mma16816h(acc[0][2], al0, bh1[0], bh1[1]);
            mma16816h(acc[0][3], al0, bh1[2], bh1[3]);
            mma16816h(acc[1][0], al1, bh0[0], bh0[1]);
            mma16816h(acc[1][1], al1, bh0[2], bh0[3]);
            mma16816h(acc[1][2], al1, bh1[0], bh1[1]);
            mma16816h(acc[1][3], al1, bh1[2], bh1[3]);
        }

        __syncthreads();                      // all warps done reading E smem
        if (s < 3) { fetch_slab(smb, erow, s + 1, tid); CPCOMMIT(); }

        // epilogue overlaps the async fetch
#pragma unroll
        for (int n = 0; n < 4; ++n) {
            int h0 = wh * 32 + n * 8 + (lane & 3) * 2;
            float2 bse = *reinterpret_cast<const float2*>(smc + OFF_BASE + h0 * 4);
#pragma unroll
            for (int m = 0; m < 2; ++m) {
                int jr0 = s * 64 + wj * 32 + m * 16 + (lane >> 2);
                int jr1 = jr0 + 8;
                float2 vx0 = *reinterpret_cast<const float2*>(VexB + jr0 * H_ + h0);
                float2 vx1 = *reinterpret_cast<const float2*>(VexB + jr1 * H_ + h0);
                float2 vn0 = *reinterpret_cast<const float2*>(VnxB + jr0 * H_ + h0);
                float2 vn1 = *reinterpret_cast<const float2*>(VnxB + jr1 * H_ + h0);
                float et00 = acc[m][n][0] + bse.x + vx0.x;
                float et01 = acc[m][n][1] + bse.y + vx0.y;
                float et10 = acc[m][n][2] + bse.x + vx1.x;
                float et11 = acc[m][n][3] + bse.y + vx1.y;
                float g00 = 1.f / (1.f + __expf(-et00));
                float g01 = 1.f / (1.f + __expf(-et01));
                float g10 = 1.f / (1.f + __expf(-et10));
                float g11 = 1.f / (1.f + __expf(-et11));
                sN0[n] += g00 * vn0.x + g10 * vn1.x;
                sN1[n] += g01 * vn0.y + g11 * vn1.y;
                sD0[n] += g00 + g10;
                sD1[n] += g01 + g11;
                if (write_e) {
                    sS0[n] += et00 + et10;
                    sS1[n] += et01 + et11;
                    sQ0[n] += et00 * et00 + et10 * et10;
                    sQ1[n] += et01 * et01 + et11 * et11;
                    *reinterpret_cast<float2*>(etrow + (size_t)jr0 * H_ + h0) =
                        make_float2(et00, et01);
                    *reinterpret_cast<float2*>(etrow + (size_t)jr1 * H_ + h0) =
                        make_float2(et10, et11);
                }
            }
        }
    }

    // final reduction over j-lanes (xor shuffles), then smem across wj groups
    float* red = reinterpret_cast<float*>(smc + OFF_RED);
#pragma unroll
    for (int n = 0; n < 4; ++n) {
#pragma unroll
        for (int o = 4; o < 32; o <<= 1) {
            sN0[n] += __shfl_xor_sync(0xffffffffu, sN0[n], o);
            sN1[n] += __shfl_xor_sync(0xffffffffu, sN1[n], o);
            sD0[n] += __shfl_xor_sync(0xffffffffu, sD0[n], o);
            sD1[n] += __shfl_xor_sync(0xffffffffu, sD1[n], o);
        }
        if (write_e) {
#pragma unroll
            for (int o = 4; o < 32; o <<= 1) {
                sS0[n] += __shfl_xor_sync(0xffffffffu, sS0[n], o);
                sS1[n] += __shfl_xor_sync(0xffffffffu, sS1[n], o);
                sQ0[n] += __shfl_xor_sync(0xffffffffu, sQ0[n], o);
                sQ1[n] += __shfl_xor_sync(0xffffffffu, sQ1[n], o);
            }
        }
        if (lane < 4) {
            int h = wh * 32 + n * 8 + lane * 2;
            red[(0 * 2 + wj) * 128 + h]     = sN0[n];
            red[(0 * 2 + wj) * 128 + h + 1] = sN1[n];
            red[(1 * 2 + wj) * 128 + h]     = sD0[n];
            red[(1 * 2 + wj) * 128 + h + 1] = sD1[n];
            red[(2 * 2 + wj) * 128 + h]     = sS0[n];
            red[(2 * 2 + wj) * 128 + h + 1] = sS1[n];
            red[(3 * 2 + wj) * 128 + h]     = sQ0[n];
            red[(3 * 2 + wj) * 128 + h + 1] = sQ1[n];
        }
    }
    __syncthreads();
    if (tid < H_) {
        float n = red[tid] + red[128 + tid];
        float d = red[256 + tid] + red[384 + tid];
        float aggv = n / (d + 1e-20f);
        float xt = aggv + d_Unx[bi * H_ + tid];
        d_xtmp[bi * H_ + tid] = xt;
        atomicAdd(&d_stats[256 + tid], xt);
        atomicAdd(&d_stats[384 + tid], xt * xt);
        if (write_e) {
            atomicAdd(&d_stats[tid],       red[512 + tid] + red[640 + tid]);
            atomicAdd(&d_stats[128 + tid], red[768 + tid] + red[896 + tid]);
        }
    }
}

// ---------------------------------------------------------------------------
// Merged update: blocks [0,512) x += relu(bn(x_tmp)); blocks [512,...) e-update
// with scale/shift recomputed inline from the global stats.
__global__ void update_kernel(const float* __restrict__ gx,
                              const float* __restrict__ bx,
                              const float* __restrict__ ge,
                              const float* __restrict__ be) {
    int bid = blockIdx.x;
    int tid = threadIdx.x;
    if (bid < 512) {
        int idx = bid * 256 + tid;            // XN_
        int h = idx & (H_ - 1);
        const float inv = 1.f / (float)BV_;
        float mu  = d_stats[256 + h] * inv;
        float var = d_stats[384 + h] * inv - mu * mu;
        float t = gx[h] * (d_xtmp[idx] - mu) * rsqrtf(var + 1e-5f) + bx[h];
        d_xbuf[idx] += fmaxf(t, 0.f);
        return;
    }
    int idx4 = (bid - 512) * 256 + tid;       // EN_/4
    int h0 = (idx4 & 31) * 4;
    const float inv = 1.f / (float)(B_ * V_ * V_);
    float4 s1 = *reinterpret_cast<const float4*>(d_stats + h0);
    float4 s2 = *reinterpret_cast<const float4*>(d_stats + 128 + h0);
    float4 g4 = *reinterpret_cast<const float4*>(ge + h0);
    float4 b4 = *reinterpret_cast<const float4*>(be + h0);
    float mux = s1.x * inv, muy = s1.y * inv, muz = s1.z * inv, muw = s1.w * inv;
    float scx = g4.x * rsqrtf(s2.x * inv - mux * mux + 1e-5f);
    float scy = g4.y * rsqrtf(s2.y * inv - muy * muy + 1e-5f);
    float scz = g4.z * rsqrtf(s2.z * inv - muz * muz + 1e-5f);
    float scw = g4.w * rsqrtf(s2.w * inv - muw * muw + 1e-5f);
    float shx = b4.x - mux * scx, shy = b4.y - muy * scy;
    float shz = b4.z - muz * scz, shw = b4.w - muw * scw;
    uint2 hi = reinterpret_cast<const uint2*>(d_ehi)[idx4];
    uint2 lo = reinterpret_cast<const uint2*>(d_elo)[idx4];
    float4 et = reinterpret_cast<const float4*>(d_etmp)[idx4];
    float2 hxy = up_h2(hi.x), hzw = up_h2(hi.y);
    float2 lxy = up_h2(lo.x), lzw = up_h2(lo.y);
    float vx = hxy.x + lxy.x + fmaxf(et.x * scx + shx, 0.f);
    float vy = hxy.y + lxy.y + fmaxf(et.y * scy + shy, 0.f);
    float vz = hzw.x + lzw.x + fmaxf(et.z * scz + shz, 0.f);
    float vw = hzw.y + lzw.y + fmaxf(et.w * scw + shw, 0.f);
    uint2 nhi, nlo;
    split2h(vx, vy, nhi.x, nlo.x);
    split2h(vz, vw, nhi.y, nlo.y);
    reinterpret_cast<uint2*>(d_ehi)[idx4] = nhi;
    reinterpret_cast<uint2*>(d_elo)[idx4] = nlo;
}

__global__ void zero_out_kernel(float* out) {
    if (threadIdx.x < B_) out[threadIdx.x] = 0.f;
}

// per (b,v): h = relu(x@W1+b1); v = h@W2 + b2; out[b] += v/V
__global__ void readout_kernel(const float* __restrict__ W1,
                               const float* __restrict__ b1,
                               const float* __restrict__ W2,
                               const float* __restrict__ b2,
                               float* __restrict__ out) {
    __shared__ float xs[H_];
    __shared__ float wred[4];
    int row = blockIdx.x;
    int tid = threadIdx.x;
    xs[tid] = d_xbuf[row * H_ + tid];
    __syncthreads();
    float acc = b1[tid];
#pragma unroll 8
    for (int k = 0; k < H_; ++k) acc += xs[k] * W1[k * H_ + tid];
    float v = fmaxf(acc, 0.f) * W2[tid];
#pragma unroll
    for (int o = 16; o > 0; o >>= 1) v += __shfl_down_sync(0xffffffffu, v, o);
    if ((tid & 31) == 0) wred[tid >> 5] = v;
    __syncthreads();
    if (tid == 0) {
        float s = wred[0] + wred[1] + wred[2] + wred[3] + b2[0];
        atomicAdd(&out[row >> 8], s * (1.f / (float)V_));
    }
}

// ---------------------------------------------------------------------------
extern "C" void kernel_launch(void* const* d_in, const int* in_sizes, int n_in,
                              void* d_out, int out_size) {
    const float* xev   = (const float*)d_in[1];
    const float* coord = (const float*)d_in[2];
    const float* tour  = (const float*)d_in[3];
    const float* btour = (const float*)d_in[4];
    const float* Wn    = (const float*)d_in[5];
    const float* bn    = (const float*)d_in[6];
    const float* Wev   = (const float*)d_in[7];
    const float* bev   = (const float*)d_in[8];
    const float* Wec   = (const float*)d_in[9];
    const float* bec   = (const float*)d_in[10];
    const float* Ue    = (const float*)d_in[11];
    const float* bUe   = (const float*)d_in[12];
    const float* Ve    = (const float*)d_in[13];
    const float* bVe   = (const float*)d_in[14];
    const float* Un    = (const float*)d_in[15];
    const float* bUn   = (const float*)d_in[16];
    const float* Vn    = (const float*)d_in[17];
    const float* bVn   = (const float*)d_in[18];
    const float* ge    = (const float*)d_in[19];
    const float* be    = (const float*)d_in[20];
    const float* gx    = (const float*)d_in[21];
    const float* bx    = (const float*)d_in[22];
    const float* W1    = (const float*)d_in[23];
    const float* b1    = (const float*)d_in[24];
    const float* W2    = (const float*)d_in[25];
    const float* b2    = (const float*)d_in[26];
    float* out = (float*)d_out;

    cudaFuncSetAttribute(fused_edge_kernel,
                         cudaFuncAttributeMaxDynamicSharedMemorySize, SMEM_F);

    node_embed_kernel<<<XN_ / 256, 256>>>(coord, Wn, bn);
    edge_embed_kernel<<<EN_ / 4 / 256, 256>>>(xev, tour, btour, Wev, bev, Wec, bec);

    for (int l = 0; l < L_; ++l) {
        prep_kernel<<<193, 128>>>(Ue + l * H_ * H_,
                                  Ve + l * H_ * H_, bVe + l * H_,
                                  Vn + l * H_ * H_, bVn + l * H_,
                                  Un + l * H_ * H_, bUn + l * H_);
        int write_e = (l < L_ - 1) ? 1 : 0;
        fused_edge_kernel<<<BV_, 256, SMEM_F>>>(bUe + l * H_, write_e);
        int nblk = 512 + (write_e ? (EN_ / 4 / 256) : 0);
        update_kernel<<<nblk, 256>>>(gx + l * H_, bx + l * H_,
                                     ge + l * H_, be + l * H_);
    }

    zero_out_kernel<<<1, 32>>>(out);
    readout_kernel<<<BV_, H_>>>(W1, b1, W2, b2, out);
}

// round 9
// speedup vs baseline: 1.2613x; 1.1972x over previous
#include <cuda_runtime.h>
#include <cuda_fp16.h>
#include <math.h>
#include <stdint.h>

// Problem constants
#define B_  4
#define V_  256
#define H_  128
#define H2_ 64
#define L_  3
#define BV_ (B_*V_)              // 1024
#define XN_ (BV_*H_)             // 131072
#define EN_ 33554432             // B*V*V*H

// Scratch (allocation-free: __device__ globals)
// e stored as a single fp16 plane; etmp fp16 (errors wash out through BN+mean)
__device__ __align__(16) __half d_eh[EN_];
__device__ __align__(16) __half d_etmp[EN_];
__device__ float d_xbuf[XN_];
__device__ float d_Vex[XN_];
__device__ float d_Vnx[XN_];
__device__ float d_Unx[XN_];
__device__ float d_xtmp[XN_];
// [0:128) e-ssum, [128:256) e-ssq, [256:384) x-sum, [384:512) x-sumsq
__device__ __align__(16) float d_stats[512];
// UeT (transposed Ue: row = output h, col = k), single fp16 plane [128][128]
__device__ __align__(16) __half d_UeTh[H_ * H_];

// ---- helpers --------------------------------------------------------------
__device__ __forceinline__ uint32_t pkh2(float a, float b) {
    __half2 t = __floats2half2_rn(a, b);
    return *reinterpret_cast<uint32_t*>(&t);
}
__device__ __forceinline__ float2 up_h2(uint32_t u) {
    __half2 t = *reinterpret_cast<__half2*>(&u);
    return make_float2(__half2float(t.x), __half2float(t.y));
}
__device__ __forceinline__ uint32_t s2u(const void* p) {
    uint32_t a;
    asm("{ .reg .u64 t; cvta.to.shared.u64 t, %1; cvt.u32.u64 %0, t; }"
        : "=r"(a) : "l"(p));
    return a;
}
__device__ __forceinline__ void mma16816h(float* d, const uint32_t* a,
                                          uint32_t b0, uint32_t b1) {
    asm volatile(
        "mma.sync.aligned.m16n8k16.row.col.f32.f16.f16.f32 "
        "{%0,%1,%2,%3}, {%4,%5,%6,%7}, {%8,%9}, {%0,%1,%2,%3};"
        : "+f"(d[0]), "+f"(d[1]), "+f"(d[2]), "+f"(d[3])
        : "r"(a[0]), "r"(a[1]), "r"(a[2]), "r"(a[3]), "r"(b0), "r"(b1));
}
__device__ __forceinline__ void ldsm4(uint32_t addr, uint32_t* r) {
    asm volatile("ldmatrix.sync.aligned.m8n8.x4.shared.b16 {%0,%1,%2,%3}, [%4];"
        : "=r"(r[0]), "=r"(r[1]), "=r"(r[2]), "=r"(r[3]) : "r"(addr));
}
#define CP16(dst, src) \
    asm volatile("cp.async.cg.shared.global [%0], [%1], 16;" :: "r"(dst), "l"(src))
#define CPCOMMIT() asm volatile("cp.async.commit_group;")

// ---------------------------------------------------------------------------
// x = coord @ W_node + b_node
__global__ void node_embed_kernel(const float* __restrict__ coord,
                                  const float* __restrict__ Wn,
                                  const float* __restrict__ bn) {
    int idx = blockIdx.x * blockDim.x + threadIdx.x;
    int h = idx & (H_ - 1);
    int row = idx >> 7;
    const float* c = coord + row * 3;
    d_xbuf[idx] = c[0] * Wn[h] + c[1] * Wn[H_ + h] + c[2] * Wn[2 * H_ + h] + bn[h];
}

// e = concat(ev*Wev + bev, tour*Wec0 + best*Wec1 + bec), single fp16 plane
__global__ void edge_embed_kernel(const float* __restrict__ ev,
                                  const float* __restrict__ tour,
                                  const float* __restrict__ btour,
                                  const float* __restrict__ Wev,
                                  const float* __restrict__ bev,
                                  const float* __restrict__ Wec,
                                  const float* __restrict__ bec) {
    int idx4 = blockIdx.x * blockDim.x + threadIdx.x;  // EN_/4
    int h4 = idx4 & 31;
    int edge = idx4 >> 5;
    int h0 = h4 * 4;
    float4 o;
    if (h0 < H2_) {
        float v = ev[edge];
        o.x = v * Wev[h0 + 0] + bev[h0 + 0];
        o.y = v * Wev[h0 + 1] + bev[h0 + 1];
        o.z = v * Wev[h0 + 2] + bev[h0 + 2];
        o.w = v * Wev[h0 + 3] + bev[h0 + 3];
    } else {
        float t = tour[edge], bt = btour[edge];
        int g = h0 - H2_;
        o.x = t * Wec[g + 0] + bt * Wec[H2_ + g + 0] + bec[g + 0];
        o.y = t * Wec[g + 1] + bt * Wec[H2_ + g + 1] + bec[g + 1];
        o.z = t * Wec[g + 2] + bt * Wec[H2_ + g + 2] + bec[g + 2];
        o.w = t * Wec[g + 3] + bt * Wec[H2_ + g + 3] + bec[g + 3];
    }
    uint2 pk;
    pk.x = pkh2(o.x, o.y);
    pk.y = pkh2(o.z, o.w);
    reinterpret_cast<uint2*>(d_eh)[idx4] = pk;
}

// Combined per-layer prep: blocks 0-63 = Vex/Vnx/Unx gemm3; 64-191 = UeT fp16;
// block 192 = zero stats.
__global__ void __launch_bounds__(128) prep_kernel(
        const float* __restrict__ Ue,
        const float* __restrict__ Ve, const float* __restrict__ bVe,
        const float* __restrict__ Vn, const float* __restrict__ bVn,
        const float* __restrict__ Un, const float* __restrict__ bUn) {
    int bid = blockIdx.x;
    int tid = threadIdx.x;
    if (bid >= 192) {
        for (int i = tid; i < 512; i += 128) d_stats[i] = 0.f;
        return;
    }
    if (bid >= 64) {
        int h = bid - 64;
        int k = tid;
        d_UeTh[h * H_ + k] = __float2half_rn(Ue[k * H_ + h]);
        return;
    }
    __shared__ float xs[16 * H_];
    int h = tid;
    int r0 = bid * 16;
    {
        const float4* src = reinterpret_cast<const float4*>(d_xbuf + r0 * H_);
        float4* dst = reinterpret_cast<float4*>(xs);
#pragma unroll
        for (int t = 0; t < 4; ++t) dst[h + t * 128] = src[h + t * 128];
    }
    __syncthreads();
    float a0[16], a1[16], a2[16];
    {
        float v0 = bVe[h], v1 = bVn[h], v2 = bUn[h];
#pragma unroll
        for (int r = 0; r < 16; ++r) { a0[r] = v0; a1[r] = v1; a2[r] = v2; }
    }
    for (int k = 0; k < H_; k += 4) {
        float w0[4], w1[4], w2[4];
#pragma unroll
        for (int q = 0; q < 4; ++q) {
            w0[q] = Ve[(k + q) * H_ + h];
            w1[q] = Vn[(k + q) * H_ + h];
            w2[q] = Un[(k + q) * H_ + h];
        }
#pragma unroll
        for (int r = 0; r < 16; ++r) {
            float4 xv = *reinterpret_cast<const float4*>(xs + r * H_ + k);
            a0[r] += xv.x * w0[0] + xv.y * w0[1] + xv.z * w0[2] + xv.w * w0[3];
            a1[r] += xv.x * w1[0] + xv.y * w1[1] + xv.z * w1[2] + xv.w * w1[3];
            a2[r] += xv.x * w2[0] + xv.y * w2[1] + xv.z * w2[2] + xv.w * w2[3];
        }
    }
#pragma unroll
    for (int r = 0; r < 16; ++r) {
        d_Vex[(r0 + r) * H_ + h] = a0[r];
        d_Vnx[(r0 + r) * H_ + h] = a1[r];
        d_Unx[(r0 + r) * H_ + h] = a2[r];
    }
}

// ---------------------------------------------------------------------------
// Fused edge layer: single fp16 E plane, 64-j slabs DOUBLE-buffered,
// warp tile 32j x 32h, ldmatrix + mma.sync, 3 CTAs/SM.
#define OFF_UH   0          // 32768 (128 rows x 256B)
#define OFF_E    32768      // 2 buffers x 16384
#define OFF_BASE 65536      // 512
#define OFF_RED  66048      // 4096
#define SMEM_F   70144

__device__ __forceinline__ void fetch_slab(uint32_t smb, size_t erow_elem,
                                           int s, int tid) {
    // 1024 x 16B chunks: 64 rows x 16 chunks
#pragma unroll
    for (int t = 0; t < 4; ++t) {
        int idx = tid + t * 256;
        int r = idx >> 4;
        int c = idx & 15;
        const __half* src = d_eh + erow_elem + (size_t)(s * 64 + r) * H_ + c * 8;
        uint32_t dst = smb + OFF_E + (s & 1) * 16384 + r * 256 + ((c ^ (r & 7)) << 4);
        CP16(dst, src);
    }
}

__global__ void __launch_bounds__(256, 3) fused_edge_kernel(
        const float* __restrict__ bUe, int write_e) {
    extern __shared__ char smc[];
    uint32_t smb = s2u(smc);
    int tid = threadIdx.x, w = tid >> 5, lane = tid & 31;
    int wj = w & 1, wh = w >> 1;
    int bi = blockIdx.x, b = bi >> 8;
    size_t erow = (size_t)bi * (V_ * H_);

    // prologue: U tile (2048 chunks) + e slab 0
#pragma unroll
    for (int t = 0; t < 8; ++t) {
        int idx = tid + t * 256;
        int hrow = idx >> 4;
        int c = idx & 15;
        const __half* src = d_UeTh + hrow * H_ + c * 8;
        uint32_t dst = smb + OFF_UH + hrow * 256 + ((c ^ (hrow & 7)) << 4);
        CP16(dst, src);
    }
    fetch_slab(smb, erow, 0, tid);
    CPCOMMIT();
    if (tid < H_)
        reinterpret_cast<float*>(smc + OFF_BASE)[tid] =
            bUe[tid] + d_Vex[bi * H_ + tid];

    const float* VexB = d_Vex + (size_t)b * V_ * H_;
    const float* VnxB = d_Vnx + (size_t)b * V_ * H_;
    __half* etrow = d_etmp + erow;

    // fragment addressing
    int ra = wj * 32 + (lane & 15);
    uint32_t aOff = (uint32_t)(ra * 256);             // within E buffer
    int am = ra & 7;
    int ach = lane >> 4;
    int rb = wh * 32 + ((lane >> 4) & 1) * 8 + (lane & 7);
    uint32_t bB0 = smb + OFF_UH + rb * 256;           // p=0
    uint32_t bB1 = bB0 + 16 * 256;                    // p=1
    int bm = rb & 7;
    int bch = (lane >> 3) & 1;

    float sN0[4], sN1[4], sD0[4], sD1[4], sS0[4], sS1[4], sQ0[4], sQ1[4];
#pragma unroll
    for (int n = 0; n < 4; ++n) {
        sN0[n] = sN1[n] = sD0[n] = sD1[n] = 0.f;
        sS0[n] = sS1[n] = sQ0[n] = sQ1[n] = 0.f;
    }

    for (int s = 0; s < 4; ++s) {
        asm volatile("cp.async.wait_group 0;");
        __syncthreads();      // all threads done reading buf (s+1)&1 (iter s-1)
        if (s < 3) { fetch_slab(smb, erow, s + 1, tid); CPCOMMIT(); }

        uint32_t ebuf = smb + OFF_E + (s & 1) * 16384 + aOff;
        float acc[2][4][4];
#pragma unroll
        for (int m = 0; m < 2; ++m)
#pragma unroll
            for (int n = 0; n < 4; ++n)
#pragma unroll
                for (int q = 0; q < 4; ++q) acc[m][n][q] = 0.f;

#pragma unroll
        for (int kk = 0; kk < 8; ++kk) {
            uint32_t ah0[4], ah1[4];
            uint32_t ao = (uint32_t)(((kk * 2 + ach) ^ am) << 4);
            ldsm4(ebuf + ao, ah0);
            ldsm4(ebuf + 16 * 256 + ao, ah1);
            uint32_t bh0[4], bh1[4];
            uint32_t bo = (uint32_t)(((kk * 2 + bch) ^ bm) << 4);
            ldsm4(bB0 + bo, bh0);
            ldsm4(bB1 + bo, bh1);
            mma16816h(acc[0][0], ah0, bh0[0], bh0[1]);
            mma16816h(acc[0][1], ah0, bh0[2], bh0[3]);
            mma16816h(acc[0][2], ah0, bh1[0], bh1[1]);
            mma16816h(acc[0][3], ah0, bh1[2], bh1[3]);
            mma16816h(acc[1][0], ah1, bh0[0], bh0[1]);
            mma16816h(acc[1][1], ah1, bh0[2], bh0[3]);
            mma16816h(acc[1][2], ah1, bh1[0], bh1[1]);
            mma16816h(acc[1][3], ah1, bh1[2], bh1[3]);
        }

        // epilogue (E smem for this buffer no longer needed; next fetch targets
        // the other buffer, so no extra sync required here)
#pragma unroll
        for (int n = 0; n < 4; ++n) {
            int h0 = wh * 32 + n * 8 + (lane & 3) * 2;
            float2 bse = *reinterpret_cast<const float2*>(smc + OFF_BASE + h0 * 4);
#pragma unroll
            for (int m = 0; m < 2; ++m) {
                int jr0 = s * 64 + wj * 32 + m * 16 + (lane >> 2);
                int jr1 = jr0 + 8;
                float2 vx0 = *reinterpret_cast<const float2*>(VexB + jr0 * H_ + h0);
                float2 vx1 = *reinterpret_cast<const float2*>(VexB + jr1 * H_ + h0);
                float2 vn0 = *reinterpret_cast<const float2*>(VnxB + jr0 * H_ + h0);
                float2 vn1 = *reinterpret_cast<const float2*>(VnxB + jr1 * H_ + h0);
                float et00 = acc[m][n][0] + bse.x + vx0.x;
                float et01 = acc[m][n][1] + bse.y + vx0.y;
                float et10 = acc[m][n][2] + bse.x + vx1.x;
                float et11 = acc[m][n][3] + bse.y + vx1.y;
                float g00 = 1.f / (1.f + __expf(-et00));
                float g01 = 1.f / (1.f + __expf(-et01));
                float g10 = 1.f / (1.f + __expf(-et10));
                float g11 = 1.f / (1.f + __expf(-et11));
                sN0[n] += g00 * vn0.x + g10 * vn1.x;
                sN1[n] += g01 * vn0.y + g11 * vn1.y;
                sD0[n] += g00 + g10;
                sD1[n] += g01 + g11;
                if (write_e) {
                    sS0[n] += et00 + et10;
                    sS1[n] += et01 + et11;
                    sQ0[n] += et00 * et00 + et10 * et10;
                    sQ1[n] += et01 * et01 + et11 * et11;
                    *reinterpret_cast<__half2*>(etrow + (size_t)jr0 * H_ + h0) =
                        __floats2half2_rn(et00, et01);
                    *reinterpret_cast<__half2*>(etrow + (size_t)jr1 * H_ + h0) =
                        __floats2half2_rn(et10, et11);
                }
            }
        }
    }

    // final reduction over j-lanes (xor shuffles), then smem across wj groups
    float* red = reinterpret_cast<float*>(smc + OFF_RED);
#pragma unroll
    for (int n = 0; n < 4; ++n) {
#pragma unroll
        for (int o = 4; o < 32; o <<= 1) {
            sN0[n] += __shfl_xor_sync(0xffffffffu, sN0[n], o);
            sN1[n] += __shfl_xor_sync(0xffffffffu, sN1[n], o);
            sD0[n] += __shfl_xor_sync(0xffffffffu, sD0[n], o);
            sD1[n] += __shfl_xor_sync(0xffffffffu, sD1[n], o);
        }
        if (write_e) {
#pragma unroll
            for (int o = 4; o < 32; o <<= 1) {
                sS0[n] += __shfl_xor_sync(0xffffffffu, sS0[n], o);
                sS1[n] += __shfl_xor_sync(0xffffffffu, sS1[n], o);
                sQ0[n] += __shfl_xor_sync(0xffffffffu, sQ0[n], o);
                sQ1[n] += __shfl_xor_sync(0xffffffffu, sQ1[n], o);
            }
        }
        if (lane < 4) {
            int h = wh * 32 + n * 8 + lane * 2;
            red[(0 * 2 + wj) * 128 + h]     = sN0[n];
            red[(0 * 2 + wj) * 128 + h + 1] = sN1[n];
            red[(1 * 2 + wj) * 128 + h]     = sD0[n];
            red[(1 * 2 + wj) * 128 + h + 1] = sD1[n];
            red[(2 * 2 + wj) * 128 + h]     = sS0[n];
            red[(2 * 2 + wj) * 128 + h + 1] = sS1[n];
            red[(3 * 2 + wj) * 128 + h]     = sQ0[n];
            red[(3 * 2 + wj) * 128 + h + 1] = sQ1[n];
        }
    }
    __syncthreads();
    if (tid < H_) {
        float n = red[tid] + red[128 + tid];
        float d = red[256 + tid] + red[384 + tid];
        float aggv = n / (d + 1e-20f);
        float xt = aggv + d_Unx[bi * H_ + tid];
        d_xtmp[bi * H_ + tid] = xt;
        atomicAdd(&d_stats[256 + tid], xt);
        atomicAdd(&d_stats[384 + tid], xt * xt);
        if (write_e) {
            atomicAdd(&d_stats[tid],       red[512 + tid] + red[640 + tid]);
            atomicAdd(&d_stats[128 + tid], red[768 + tid] + red[896 + tid]);
        }
    }
}

// ---------------------------------------------------------------------------
// Merged update: blocks [0,512) x += relu(bn(x_tmp)); blocks [512,...) e-update
// with scale/shift recomputed inline from the global stats. All-fp16 e path.
__global__ void update_kernel(const float* __restrict__ gx,
                              const float* __restrict__ bx,
                              const float* __restrict__ ge,
                              const float* __restrict__ be) {
    int bid = blockIdx.x;
    int tid = threadIdx.x;
    if (bid < 512) {
        int idx = bid * 256 + tid;            // XN_
        int h = idx & (H_ - 1);
        const float inv = 1.f / (float)BV_;
        float mu  = d_stats[256 + h] * inv;
        float var = d_stats[384 + h] * inv - mu * mu;
        float t = gx[h] * (d_xtmp[idx] - mu) * rsqrtf(var + 1e-5f) + bx[h];
        d_xbuf[idx] += fmaxf(t, 0.f);
        return;
    }
    int idx4 = (bid - 512) * 256 + tid;       // EN_/4
    int h0 = (idx4 & 31) * 4;
    const float inv = 1.f / (float)(B_ * V_ * V_);
    float4 s1 = *reinterpret_cast<const float4*>(d_stats + h0);
    float4 s2 = *reinterpret_cast<const float4*>(d_stats + 128 + h0);
    float4 g4 = *reinterpret_cast<const float4*>(ge + h0);
    float4 b4 = *reinterpret_cast<const float4*>(be + h0);
    float mux = s1.x * inv, muy = s1.y * inv, muz = s1.z * inv, muw = s1.w * inv;
    float scx = g4.x * rsqrtf(s2.x * inv - mux * mux + 1e-5f);
    float scy = g4.y * rsqrtf(s2.y * inv - muy * muy + 1e-5f);
    float scz = g4.z * rsqrtf(s2.z * inv - muz * muz + 1e-5f);
    float scw = g4.w * rsqrtf(s2.w * inv - muw * muw + 1e-5f);
    float shx = b4.x - mux * scx, shy = b4.y - muy * scy;
    float shz = b4.z - muz * scz, shw = b4.w - muw * scw;
    uint2 eh = reinterpret_cast<const uint2*>(d_eh)[idx4];
    uint2 et = reinterpret_cast<const uint2*>(d_etmp)[idx4];
    float2 exy = up_h2(eh.x), ezw = up_h2(eh.y);
    float2 txy = up_h2(et.x), tzw = up_h2(et.y);
    float vx = exy.x + fmaxf(txy.x * scx + shx, 0.f);
    float vy = exy.y + fmaxf(txy.y * scy + shy, 0.f);
    float vz = ezw.x + fmaxf(tzw.x * scz + shz, 0.f);
    float vw = ezw.y + fmaxf(tzw.y * scw + shw, 0.f);
    uint2 pk;
    pk.x = pkh2(vx, vy);
    pk.y = pkh2(vz, vw);
    reinterpret_cast<uint2*>(d_eh)[idx4] = pk;
}

__global__ void zero_out_kernel(float* out) {
    if (threadIdx.x < B_) out[threadIdx.x] = 0.f;
}

// per (b,v): h = relu(x@W1+b1); v = h@W2 + b2; out[b] += v/V
__global__ void readout_kernel(const float* __restrict__ W1,
                               const float* __restrict__ b1,
                               const float* __restrict__ W2,
                               const float* __restrict__ b2,
                               float* __restrict__ out) {
    __shared__ float xs[H_];
    __shared__ float wred[4];
    int row = blockIdx.x;
    int tid = threadIdx.x;
    xs[tid] = d_xbuf[row * H_ + tid];
    __syncthreads();
    float acc = b1[tid];
#pragma unroll 8
    for (int k = 0; k < H_; ++k) acc += xs[k] * W1[k * H_ + tid];
    float v = fmaxf(acc, 0.f) * W2[tid];
#pragma unroll
    for (int o = 16; o > 0; o >>= 1) v += __shfl_down_sync(0xffffffffu, v, o);
    if ((tid & 31) == 0) wred[tid >> 5] = v;
    __syncthreads();
    if (tid == 0) {
        float s = wred[0] + wred[1] + wred[2] + wred[3] + b2[0];
        atomicAdd(&out[row >> 8], s * (1.f / (float)V_));
    }
}

// ---------------------------------------------------------------------------
extern "C" void kernel_launch(void* const* d_in, const int* in_sizes, int n_in,
                              void* d_out, int out_size) {
    const float* xev   = (const float*)d_in[1];
    const float* coord = (const float*)d_in[2];
    const float* tour  = (const float*)d_in[3];
    const float* btour = (const float*)d_in[4];
    const float* Wn    = (const float*)d_in[5];
    const float* bn    = (const float*)d_in[6];
    const float* Wev   = (const float*)d_in[7];
    const float* bev   = (const float*)d_in[8];
    const float* Wec   = (const float*)d_in[9];
    const float* bec   = (const float*)d_in[10];
    const float* Ue    = (const float*)d_in[11];
    const float* bUe   = (const float*)d_in[12];
    const float* Ve    = (const float*)d_in[13];
    const float* bVe   = (const float*)d_in[14];
    const float* Un    = (const float*)d_in[15];
    const float* bUn   = (const float*)d_in[16];
    const float* Vn    = (const float*)d_in[17];
    const float* bVn   = (const float*)d_in[18];
    const float* ge    = (const float*)d_in[19];
    const float* be    = (const float*)d_in[20];
    const float* gx    = (const float*)d_in[21];
    const float* bx    = (const float*)d_in[22];
    const float* W1    = (const float*)d_in[23];
    const float* b1    = (const float*)d_in[24];
    const float* W2    = (const float*)d_in[25];
    const float* b2    = (const float*)d_in[26];
    float* out = (float*)d_out;

    cudaFuncSetAttribute(fused_edge_kernel,
                         cudaFuncAttributeMaxDynamicSharedMemorySize, SMEM_F);

    node_embed_kernel<<<XN_ / 256, 256>>>(coord, Wn, bn);
    edge_embed_kernel<<<EN_ / 4 / 256, 256>>>(xev, tour, btour, Wev, bev, Wec, bec);

    for (int l = 0; l < L_; ++l) {
        prep_kernel<<<193, 128>>>(Ue + l * H_ * H_,
                                  Ve + l * H_ * H_, bVe + l * H_,
                                  Vn + l * H_ * H_, bVn + l * H_,
                                  Un + l * H_ * H_, bUn + l * H_);
        int write_e = (l < L_ - 1) ? 1 : 0;
        fused_edge_kernel<<<BV_, 256, SMEM_F>>>(bUe + l * H_, write_e);
        int nblk = 512 + (write_e ? (EN_ / 4 / 256) : 0);
        update_kernel<<<nblk, 256>>>(gx + l * H_, bx + l * H_,
                                     ge + l * H_, be + l * H_);
    }

    zero_out_kernel<<<1, 32>>>(out);
    readout_kernel<<<BV_, H_>>>(W1, b1, W2, b2, out);
}

// round 10
// speedup vs baseline: 1.3425x; 1.0644x over previous
#include <cuda_runtime.h>
#include <cuda_fp16.h>
#include <math.h>
#include <stdint.h>

// Problem constants
#define B_  4
#define V_  256
#define H_  128
#define H2_ 64
#define L_  3
#define BV_ (B_*V_)              // 1024
#define XN_ (BV_*H_)             // 131072
#define EN_ 33554432             // B*V*V*H

// ---------------------------------------------------------------------------
// TILED fp16 layout: [rows][128] stored as 8x8 blocks (64 halves = 128 B).
//   off_half(r,c) = ((r>>3)*16 + (c>>3))*64 + (r&7)*8 + (c&7)
// One MMA-fragment warp access = one 128B line.
// ---------------------------------------------------------------------------

// Scratch (allocation-free: __device__ globals)
__device__ __align__(16) __half d_eh[EN_];     // e, tiled fp16
__device__ __align__(16) __half d_etmp[EN_];   // e_tmp, tiled fp16
__device__ float d_xbuf[XN_];
__device__ float d_Vex[XN_];                   // fp32 (row bi read for base)
__device__ __align__(16) __half d_VexT[XN_];   // tiled fp16 per-b planes
__device__ __align__(16) __half d_VnxT[XN_];
__device__ float d_Unx[XN_];
__device__ float d_xtmp[XN_];
// [0:128) e-ssum, [128:256) e-ssq, [256:384) x-sum, [384:512) x-sumsq
__device__ __align__(16) float d_stats[512];
// UeT (transposed Ue: row = output h, col = k), single fp16 plane [128][128]
__device__ __align__(16) __half d_UeTh[H_ * H_];

// ---- helpers --------------------------------------------------------------
__device__ __forceinline__ uint32_t pkh2(float a, float b) {
    __half2 t = __floats2half2_rn(a, b);
    return *reinterpret_cast<uint32_t*>(&t);
}
__device__ __forceinline__ float2 up_h2(uint32_t u) {
    __half2 t = *reinterpret_cast<__half2*>(&u);
    return make_float2(__half2float(t.x), __half2float(t.y));
}
__device__ __forceinline__ uint32_t s2u(const void* p) {
    uint32_t a;
    asm("{ .reg .u64 t; cvta.to.shared.u64 t, %1; cvt.u32.u64 %0, t; }"
        : "=r"(a) : "l"(p));
    return a;
}
__device__ __forceinline__ void mma16816h(float* d, const uint32_t* a,
                                          uint32_t b0, uint32_t b1) {
    asm volatile(
        "mma.sync.aligned.m16n8k16.row.col.f32.f16.f16.f32 "
        "{%0,%1,%2,%3}, {%4,%5,%6,%7}, {%8,%9}, {%0,%1,%2,%3};"
        : "+f"(d[0]), "+f"(d[1]), "+f"(d[2]), "+f"(d[3])
        : "r"(a[0]), "r"(a[1]), "r"(a[2]), "r"(a[3]), "r"(b0), "r"(b1));
}
__device__ __forceinline__ void ldsm4(uint32_t addr, uint32_t* r) {
    asm volatile("ldmatrix.sync.aligned.m8n8.x4.shared.b16 {%0,%1,%2,%3}, [%4];"
        : "=r"(r[0]), "=r"(r[1]), "=r"(r[2]), "=r"(r[3]) : "r"(addr));
}
#define CP16(dst, src) \
    asm volatile("cp.async.cg.shared.global [%0], [%1], 16;" :: "r"(dst), "l"(src))
#define CPCOMMIT() asm volatile("cp.async.commit_group;")

// ---------------------------------------------------------------------------
// x = coord @ W_node + b_node
__global__ void node_embed_kernel(const float* __restrict__ coord,
                                  const float* __restrict__ Wn,
                                  const float* __restrict__ bn) {
    int idx = blockIdx.x * blockDim.x + threadIdx.x;
    int h = idx & (H_ - 1);
    int row = idx >> 7;
    const float* c = coord + row * 3;
    d_xbuf[idx] = c[0] * Wn[h] + c[1] * Wn[H_ + h] + c[2] * Wn[2 * H_ + h] + bn[h];
}

// e = concat(ev*Wev + bev, tour*Wec0 + best*Wec1 + bec), TILED fp16
__global__ void edge_embed_kernel(const float* __restrict__ ev,
                                  const float* __restrict__ tour,
                                  const float* __restrict__ btour,
                                  const float* __restrict__ Wev,
                                  const float* __restrict__ bev,
                                  const float* __restrict__ Wec,
                                  const float* __restrict__ bec) {
    int idx4 = blockIdx.x * blockDim.x + threadIdx.x;  // uint2 units, EN_/4
    int bi = idx4 >> 13;                 // (b,i) row, 8192 uint2 each
    int local4 = idx4 & 8191;
    int block = local4 >> 4;             // 0..511 = jb*16 + hb
    int q = local4 & 15;
    int j = (block >> 4) * 8 + (q >> 1);
    int h0 = (block & 15) * 8 + (q & 1) * 4;
    int edge = bi * 256 + j;
    float4 o;
    if (h0 < H2_) {
        float v = ev[edge];
        o.x = v * Wev[h0 + 0] + bev[h0 + 0];
        o.y = v * Wev[h0 + 1] + bev[h0 + 1];
        o.z = v * Wev[h0 + 2] + bev[h0 + 2];
        o.w = v * Wev[h0 + 3] + bev[h0 + 3];
    } else {
        float t = tour[edge], bt = btour[edge];
        int g = h0 - H2_;
        o.x = t * Wec[g + 0] + bt * Wec[H2_ + g + 0] + bec[g + 0];
        o.y = t * Wec[g + 1] + bt * Wec[H2_ + g + 1] + bec[g + 1];
        o.z = t * Wec[g + 2] + bt * Wec[H2_ + g + 2] + bec[g + 2];
        o.w = t * Wec[g + 3] + bt * Wec[H2_ + g + 3] + bec[g + 3];
    }
    uint2 pk;
    pk.x = pkh2(o.x, o.y);
    pk.y = pkh2(o.z, o.w);
    reinterpret_cast<uint2*>(d_eh)[idx4] = pk;
}

// Combined per-layer prep: blocks 0-63 = Vex/Vnx/Unx gemm3 (+tiled fp16 copies);
// 64-191 = UeT fp16; block 192 = zero stats.
__global__ void __launch_bounds__(128) prep_kernel(
        const float* __restrict__ Ue,
        const float* __restrict__ Ve, const float* __restrict__ bVe,
        const float* __restrict__ Vn, const float* __restrict__ bVn,
        const float* __restrict__ Un, const float* __restrict__ bUn) {
    int bid = blockIdx.x;
    int tid = threadIdx.x;
    if (bid >= 192) {
        for (int i = tid; i < 512; i += 128) d_stats[i] = 0.f;
        return;
    }
    if (bid >= 64) {
        int h = bid - 64;
        int k = tid;
        d_UeTh[h * H_ + k] = __float2half_rn(Ue[k * H_ + h]);
        return;
    }
    __shared__ float xs[16 * H_];
    int h = tid;
    int r0 = bid * 16;
    {
        const float4* src = reinterpret_cast<const float4*>(d_xbuf + r0 * H_);
        float4* dst = reinterpret_cast<float4*>(xs);
#pragma unroll
        for (int t = 0; t < 4; ++t) dst[h + t * 128] = src[h + t * 128];
    }
    __syncthreads();
    float a0[16], a1[16], a2[16];
    {
        float v0 = bVe[h], v1 = bVn[h], v2 = bUn[h];
#pragma unroll
        for (int r = 0; r < 16; ++r) { a0[r] = v0; a1[r] = v1; a2[r] = v2; }
    }
    for (int k = 0; k < H_; k += 4) {
        float w0[4], w1[4], w2[4];
#pragma unroll
        for (int q = 0; q < 4; ++q) {
            w0[q] = Ve[(k + q) * H_ + h];
            w1[q] = Vn[(k + q) * H_ + h];
            w2[q] = Un[(k + q) * H_ + h];
        }
#pragma unroll
        for (int r = 0; r < 16; ++r) {
            float4 xv = *reinterpret_cast<const float4*>(xs + r * H_ + k);
            a0[r] += xv.x * w0[0] + xv.y * w0[1] + xv.z * w0[2] + xv.w * w0[3];
            a1[r] += xv.x * w1[0] + xv.y * w1[1] + xv.z * w1[2] + xv.w * w1[3];
            a2[r] += xv.x * w2[0] + xv.y * w2[1] + xv.z * w2[2] + xv.w * w2[3];
        }
    }
    int bb = r0 >> 8;                       // batch of this row block
    size_t pbase = (size_t)bb * 32768;      // per-b tiled plane (halves)
#pragma unroll
    for (int r = 0; r < 16; ++r) {
        int row = r0 + r;
        d_Vex[row * H_ + h] = a0[r];
        d_Unx[row * H_ + h] = a2[r];
        int j = row & 255;
        size_t off = pbase +
            (size_t)(((j >> 3) * 16 + (h >> 3)) * 64 + (j & 7) * 8 + (h & 7));
        d_VexT[off] = __float2half_rn(a0[r]);
        d_VnxT[off] = __float2half_rn(a1[r]);
    }
}

// ---------------------------------------------------------------------------
// Fused edge layer: tiled fp16 E plane, 64-j slabs double-buffered,
// warp tile 32j x 32h, ldmatrix + mma.sync, 3 CTAs/SM.
// Epilogue loads/stores = one 128B line per warp transaction (tiled layouts).
#define OFF_UH   0          // 32768 (128 rows x 256B)
#define OFF_E    32768      // 2 buffers x 16384
#define OFF_BASE 65536      // 512
#define OFF_RED  66048      // 4096
#define SMEM_F   70144

__device__ __forceinline__ void fetch_slab(uint32_t smb, size_t erow_half,
                                           int s, int tid) {
    // 1024 x 16B chunks; idx = jb(3) | kb(4) | jr(3); src tiled, dst swizzled.
#pragma unroll
    for (int t = 0; t < 4; ++t) {
        int idx = tid + t * 256;
        int jb = idx >> 7;
        int kb = (idx >> 3) & 15;
        int jr = idx & 7;
        const __half* src = d_eh + erow_half +
            (size_t)((((s * 8 + jb) * 16 + kb) * 64) + jr * 8);
        int rl = jb * 8 + jr;
        uint32_t dst = smb + OFF_E + (s & 1) * 16384 + rl * 256 +
                       ((kb ^ (rl & 7)) << 4);
        CP16(dst, src);
    }
}

__global__ void __launch_bounds__(256, 3) fused_edge_kernel(
        const float* __restrict__ bUe, int write_e) {
    extern __shared__ char smc[];
    uint32_t smb = s2u(smc);
    int tid = threadIdx.x, w = tid >> 5, lane = tid & 31;
    int wj = w & 1, wh = w >> 1;
    int bi = blockIdx.x, b = bi >> 8;
    size_t erow = (size_t)bi * (V_ * H_);   // halves

    // prologue: U tile (2048 chunks) + e slab 0
#pragma unroll
    for (int t = 0; t < 8; ++t) {
        int idx = tid + t * 256;
        int hrow = idx >> 4;
        int c = idx & 15;
        const __half* src = d_UeTh + hrow * H_ + c * 8;
        uint32_t dst = smb + OFF_UH + hrow * 256 + ((c ^ (hrow & 7)) << 4);
        CP16(dst, src);
    }
    fetch_slab(smb, erow, 0, tid);
    CPCOMMIT();
    if (tid < H_)
        reinterpret_cast<float*>(smc + OFF_BASE)[tid] =
            bUe[tid] + d_Vex[bi * H_ + tid];

    const uint32_t* VxT =
        reinterpret_cast<const uint32_t*>(d_VexT) + (size_t)b * 16384;
    const uint32_t* VnT =
        reinterpret_cast<const uint32_t*>(d_VnxT) + (size_t)b * 16384;
    uint32_t* EtT = reinterpret_cast<uint32_t*>(d_etmp) + (size_t)bi * 16384;

    // fragment addressing (smem, unchanged)
    int ra = wj * 32 + (lane & 15);
    uint32_t aOff = (uint32_t)(ra * 256);
    int am = ra & 7;
    int ach = lane >> 4;
    int rb = wh * 32 + ((lane >> 4) & 1) * 8 + (lane & 7);
    uint32_t bB0 = smb + OFF_UH + rb * 256;
    uint32_t bB1 = bB0 + 16 * 256;
    int bm = rb & 7;
    int bch = (lane >> 3) & 1;

    float sN0[4], sN1[4], sD0[4], sD1[4], sS0[4], sS1[4], sQ0[4], sQ1[4];
#pragma unroll
    for (int n = 0; n < 4; ++n) {
        sN0[n] = sN1[n] = sD0[n] = sD1[n] = 0.f;
        sS0[n] = sS1[n] = sQ0[n] = sQ1[n] = 0.f;
    }

    for (int s = 0; s < 4; ++s) {
        asm volatile("cp.async.wait_group 0;");
        __syncthreads();
        if (s < 3) { fetch_slab(smb, erow, s + 1, tid); CPCOMMIT(); }

        uint32_t ebuf = smb + OFF_E + (s & 1) * 16384 + aOff;
        float acc[2][4][4];
#pragma unroll
        for (int m = 0; m < 2; ++m)
#pragma unroll
            for (int n = 0; n < 4; ++n)
#pragma unroll
                for (int q = 0; q < 4; ++q) acc[m][n][q] = 0.f;

#pragma unroll
        for (int kk = 0; kk < 8; ++kk) {
            uint32_t ah0[4], ah1[4];
            uint32_t ao = (uint32_t)(((kk * 2 + ach) ^ am) << 4);
            ldsm4(ebuf + ao, ah0);
            ldsm4(ebuf + 16 * 256 + ao, ah1);
            uint32_t bh0[4], bh1[4];
            uint32_t bo = (uint32_t)(((kk * 2 + bch) ^ bm) << 4);
            ldsm4(bB0 + bo, bh0);
            ldsm4(bB1 + bo, bh1);
            mma16816h(acc[0][0], ah0, bh0[0], bh0[1]);
            mma16816h(acc[0][1], ah0, bh0[2], bh0[3]);
            mma16816h(acc[0][2], ah0, bh1[0], bh1[1]);
            mma16816h(acc[0][3], ah0, bh1[2], bh1[3]);
            mma16816h(acc[1][0], ah1, bh0[0], bh0[1]);
            mma16816h(acc[1][1], ah1, bh0[2], bh0[3]);
            mma16816h(acc[1][2], ah1, bh1[0], bh1[1]);
            mma16816h(acc[1][3], ah1, bh1[2], bh1[3]);
        }

        // epilogue: tiled global accesses — one 128B line per warp transaction
#pragma unroll
        for (int n = 0; n < 4; ++n) {
            int h0 = wh * 32 + n * 8 + (lane & 3) * 2;
            float2 bse = *reinterpret_cast<const float2*>(smc + OFF_BASE + h0 * 4);
#pragma unroll
            for (int m = 0; m < 2; ++m) {
                int blk = (s * 8 + wj * 4 + m * 2) * 16 + (wh * 4 + n);
                float2 vx0 = up_h2(VxT[blk * 32 + lane]);
                float2 vx1 = up_h2(VxT[(blk + 16) * 32 + lane]);
                float2 vn0 = up_h2(VnT[blk * 32 + lane]);
                float2 vn1 = up_h2(VnT[(blk + 16) * 32 + lane]);
                float et00 = acc[m][n][0] + bse.x + vx0.x;
                float et01 = acc[m][n][1] + bse.y + vx0.y;
                float et10 = acc[m][n][2] + bse.x + vx1.x;
                float et11 = acc[m][n][3] + bse.y + vx1.y;
                float g00 = 1.f / (1.f + __expf(-et00));
                float g01 = 1.f / (1.f + __expf(-et01));
                float g10 = 1.f / (1.f + __expf(-et10));
                float g11 = 1.f / (1.f + __expf(-et11));
                sN0[n] += g00 * vn0.x + g10 * vn1.x;
                sN1[n] += g01 * vn0.y + g11 * vn1.y;
                sD0[n] += g00 + g10;
                sD1[n] += g01 + g11;
                if (write_e) {
                    sS0[n] += et00 + et10;
                    sS1[n] += et01 + et11;
                    sQ0[n] += et00 * et00 + et10 * et10;
                    sQ1[n] += et01 * et01 + et11 * et11;
                    EtT[blk * 32 + lane] = pkh2(et00, et01);
                    EtT[(blk + 16) * 32 + lane] = pkh2(et10, et11);
                }
            }
        }
    }

    // final reduction over j-lanes (xor shuffles), then smem across wj groups
    float* red = reinterpret_cast<float*>(smc + OFF_RED);
#pragma unroll
    for (int n = 0; n < 4; ++n) {
#pragma unroll
        for (int o = 4; o < 32; o <<= 1) {
            sN0[n] += __shfl_xor_sync(0xffffffffu, sN0[n], o);
            sN1[n] += __shfl_xor_sync(0xffffffffu, sN1[n], o);
            sD0[n] += __shfl_xor_sync(0xffffffffu, sD0[n], o);
            sD1[n] += __shfl_xor_sync(0xffffffffu, sD1[n], o);
        }
        if (write_e) {
#pragma unroll
            for (int o = 4; o < 32; o <<= 1) {
                sS0[n] += __shfl_xor_sync(0xffffffffu, sS0[n], o);
                sS1[n] += __shfl_xor_sync(0xffffffffu, sS1[n], o);
                sQ0[n] += __shfl_xor_sync(0xffffffffu, sQ0[n], o);
                sQ1[n] += __shfl_xor_sync(0xffffffffu, sQ1[n], o);
            }
        }
        if (lane < 4) {
            int h = wh * 32 + n * 8 + lane * 2;
            red[(0 * 2 + wj) * 128 + h]     = sN0[n];
            red[(0 * 2 + wj) * 128 + h + 1] = sN1[n];
            red[(1 * 2 + wj) * 128 + h]     = sD0[n];
            red[(1 * 2 + wj) * 128 + h + 1] = sD1[n];
            red[(2 * 2 + wj) * 128 + h]     = sS0[n];
            red[(2 * 2 + wj) * 128 + h + 1] = sS1[n];
            red[(3 * 2 + wj) * 128 + h]     = sQ0[n];
            red[(3 * 2 + wj) * 128 + h + 1] = sQ1[n];
        }
    }
    __syncthreads();
    if (tid < H_) {
        float n = red[tid] + red[128 + tid];
        float d = red[256 + tid] + red[384 + tid];
        float aggv = n / (d + 1e-20f);
        float xt = aggv + d_Unx[bi * H_ + tid];
        d_xtmp[bi * H_ + tid] = xt;
        atomicAdd(&d_stats[256 + tid], xt);
        atomicAdd(&d_stats[384 + tid], xt * xt);
        if (write_e) {
            atomicAdd(&d_stats[tid],       red[512 + tid] + red[640 + tid]);
            atomicAdd(&d_stats[128 + tid], red[768 + tid] + red[896 + tid]);
        }
    }
}

// ---------------------------------------------------------------------------
// Merged update: blocks [0,512) x += relu(bn(x_tmp)); blocks [512,...) e-update
// in tiled fp16 layout, scale/shift recomputed inline from the global stats.
__global__ void update_kernel(const float* __restrict__ gx,
                              const float* __restrict__ bx,
                              const float* __restrict__ ge,
                              const float* __restrict__ be) {
    int bid = blockIdx.x;
    int tid = threadIdx.x;
    if (bid < 512) {
        int idx = bid * 256 + tid;            // XN_
        int h = idx & (H_ - 1);
        const float inv = 1.f / (float)BV_;
        float mu  = d_stats[256 + h] * inv;
        float var = d_stats[384 + h] * inv - mu * mu;
        float t = gx[h] * (d_xtmp[idx] - mu) * rsqrtf(var + 1e-5f) + bx[h];
        d_xbuf[idx] += fmaxf(t, 0.f);
        return;
    }
    int idx4 = (bid - 512) * 256 + tid;       // uint2 units, EN_/4
    int local4 = idx4 & 8191;
    int q = local4 & 15;
    int hb = (local4 >> 4) & 15;
    int h0 = hb * 8 + (q & 1) * 4;
    const float inv = 1.f / (float)(B_ * V_ * V_);
    float4 s1 = *reinterpret_cast<const float4*>(d_stats + h0);
    float4 s2 = *reinterpret_cast<const float4*>(d_stats + 128 + h0);
    float4 g4 = *reinterpret_cast<const float4*>(ge + h0);
    float4 b4 = *reinterpret_cast<const float4*>(be + h0);
    float mux = s1.x * inv, muy = s1.y * inv, muz = s1.z * inv, muw = s1.w * inv;
    float scx = g4.x * rsqrtf(s2.x * inv - mux * mux + 1e-5f);
    float scy = g4.y * rsqrtf(s2.y * inv - muy * muy + 1e-5f);
    float scz = g4.z * rsqrtf(s2.z * inv - muz * muz + 1e-5f);
    float scw = g4.w * rsqrtf(s2.w * inv - muw * muw + 1e-5f);
    float shx = b4.x - mux * scx, shy = b4.y - muy * scy;
    float shz = b4.z - muz * scz, shw = b4.w - muw * scw;
    uint2 eh = reinterpret_cast<const uint2*>(d_eh)[idx4];
    uint2 et = reinterpret_cast<const uint2*>(d_etmp)[idx4];
    float2 exy = up_h2(eh.x), ezw = up_h2(eh.y);
    float2 txy = up_h2(et.x), tzw = up_h2(et.y);
    float vx = exy.x + fmaxf(txy.x * scx + shx, 0.f);
    float vy = exy.y + fmaxf(txy.y * scy + shy, 0.f);
    float vz = ezw.x + fmaxf(tzw.x * scz + shz, 0.f);
    float vw = ezw.y + fmaxf(tzw.y * scw + shw, 0.f);
    uint2 pk;
    pk.x = pkh2(vx, vy);
    pk.y = pkh2(vz, vw);
    reinterpret_cast<uint2*>(d_eh)[idx4] = pk;
}

__global__ void zero_out_kernel(float* out) {
    if (threadIdx.x < B_) out[threadIdx.x] = 0.f;
}

// per (b,v): h = relu(x@W1+b1); v = h@W2 + b2; out[b] += v/V
__global__ void readout_kernel(const float* __restrict__ W1,
                               const float* __restrict__ b1,
                               const float* __restrict__ W2,
                               const float* __restrict__ b2,
                               float* __restrict__ out) {
    __shared__ float xs[H_];
    __shared__ float wred[4];
    int row = blockIdx.x;
    int tid = threadIdx.x;
    xs[tid] = d_xbuf[row * H_ + tid];
    __syncthreads();
    float acc = b1[tid];
#pragma unroll 8
    for (int k = 0; k < H_; ++k) acc += xs[k] * W1[k * H_ + tid];
    float v = fmaxf(acc, 0.f) * W2[tid];
#pragma unroll
    for (int o = 16; o > 0; o >>= 1) v += __shfl_down_sync(0xffffffffu, v, o);
    if ((tid & 31) == 0) wred[tid >> 5] = v;
    __syncthreads();
    if (tid == 0) {
        float s = wred[0] + wred[1] + wred[2] + wred[3] + b2[0];
        atomicAdd(&out[row >> 8], s * (1.f / (float)V_));
    }
}

// ---------------------------------------------------------------------------
extern "C" void kernel_launch(void* const* d_in, const int* in_sizes, int n_in,
                              void* d_out, int out_size) {
    const float* xev   = (const float*)d_in[1];
    const float* coord = (const float*)d_in[2];
    const float* tour  = (const float*)d_in[3];
    const float* btour = (const float*)d_in[4];
    const float* Wn    = (const float*)d_in[5];
    const float* bn    = (const float*)d_in[6];
    const float* Wev   = (const float*)d_in[7];
    const float* bev   = (const float*)d_in[8];
    const float* Wec   = (const float*)d_in[9];
    const float* bec   = (const float*)d_in[10];
    const float* Ue    = (const float*)d_in[11];
    const float* bUe   = (const float*)d_in[12];
    const float* Ve    = (const float*)d_in[13];
    const float* bVe   = (const float*)d_in[14];
    const float* Un    = (const float*)d_in[15];
    const float* bUn   = (const float*)d_in[16];
    const float* Vn    = (const float*)d_in[17];
    const float* bVn   = (const float*)d_in[18];
    const float* ge    = (const float*)d_in[19];
    const float* be    = (const float*)d_in[20];
    const float* gx    = (const float*)d_in[21];
    const float* bx    = (const float*)d_in[22];
    const float* W1    = (const float*)d_in[23];
    const float* b1    = (const float*)d_in[24];
    const float* W2    = (const float*)d_in[25];
    const float* b2    = (const float*)d_in[26];
    float* out = (float*)d_out;

    cudaFuncSetAttribute(fused_edge_kernel,
                         cudaFuncAttributeMaxDynamicSharedMemorySize, SMEM_F);

    node_embed_kernel<<<XN_ / 256, 256>>>(coord, Wn, bn);
    edge_embed_kernel<<<EN_ / 4 / 256, 256>>>(xev, tour, btour, Wev, bev, Wec, bec);

    for (int l = 0; l < L_; ++l) {
        prep_kernel<<<193, 128>>>(Ue + l * H_ * H_,
                                  Ve + l * H_ * H_, bVe + l * H_,
                                  Vn + l * H_ * H_, bVn + l * H_,
                                  Un + l * H_ * H_, bUn + l * H_);
        int write_e = (l < L_ - 1) ? 1 : 0;
        fused_edge_kernel<<<BV_, 256, SMEM_F>>>(bUe + l * H_, write_e);
        int nblk = 512 + (write_e ? (EN_ / 4 / 256) : 0);
        update_kernel<<<nblk, 256>>>(gx + l * H_, bx + l * H_,
                                     ge + l * H_, be + l * H_);
    }

    zero_out_kernel<<<1, 32>>>(out);
    readout_kernel<<<BV_, H_>>>(W1, b1, W2, b2, out);
}

// round 11
// speedup vs baseline: 1.5769x; 1.1745x over previous
#include <cuda_runtime.h>
#include <cuda_fp16.h>
#include <math.h>
#include <stdint.h>

// Problem constants
#define B_  4
#define V_  256
#define H_  128
#define H2_ 64
#define L_  3
#define BV_ (B_*V_)              // 1024
#define XN_ (BV_*H_)             // 131072
#define EN_ 33554432             // B*V*V*H

// ---------------------------------------------------------------------------
// TILED fp16 layout: [rows][128] stored as 8x8 blocks (64 halves = 128 B).
//   off_half(r,c) = ((r>>3)*16 + (c>>3))*64 + (r&7)*8 + (c&7)
// One MMA-fragment warp access = one 128B line.
// ---------------------------------------------------------------------------

// Scratch (allocation-free: __device__ globals)
__device__ __align__(16) __half d_eh[EN_];     // e, tiled fp16
__device__ __align__(16) __half d_etmp[EN_];   // e_tmp, tiled fp16
__device__ float d_xbuf[XN_];
__device__ float d_Vex[XN_];                   // fp32 (row bi read for base)
__device__ __align__(16) __half d_VexT[XN_];   // tiled fp16 per-b planes
__device__ __align__(16) __half d_VnxT[XN_];
__device__ float d_Unx[XN_];
__device__ float d_xtmp[XN_];
// [0:128) e-ssum, [128:256) e-ssq, [256:384) x-sum, [384:512) x-sumsq
__device__ __align__(16) float d_stats[512];
// UeT (transposed Ue: row = output h, col = k), single fp16 plane [128][128]
__device__ __align__(16) __half d_UeTh[H_ * H_];

// ---- helpers --------------------------------------------------------------
__device__ __forceinline__ uint32_t pkh2(float a, float b) {
    __half2 t = __floats2half2_rn(a, b);
    return *reinterpret_cast<uint32_t*>(&t);
}
__device__ __forceinline__ float2 up_h2(uint32_t u) {
    __half2 t = *reinterpret_cast<__half2*>(&u);
    return make_float2(__half2float(t.x), __half2float(t.y));
}
__device__ __forceinline__ float frcp(float x) {
    float r;
    asm("rcp.approx.f32 %0, %1;" : "=f"(r) : "f"(x));
    return r;
}
__device__ __forceinline__ float sigmoid_f(float x) {
    return frcp(1.f + __expf(-x));
}
__device__ __forceinline__ uint32_t s2u(const void* p) {
    uint32_t a;
    asm("{ .reg .u64 t; cvta.to.shared.u64 t, %1; cvt.u32.u64 %0, t; }"
        : "=r"(a) : "l"(p));
    return a;
}
__device__ __forceinline__ void mma16816h(float* d, const uint32_t* a,
                                          uint32_t b0, uint32_t b1) {
    asm volatile(
        "mma.sync.aligned.m16n8k16.row.col.f32.f16.f16.f32 "
        "{%0,%1,%2,%3}, {%4,%5,%6,%7}, {%8,%9}, {%0,%1,%2,%3};"
        : "+f"(d[0]), "+f"(d[1]), "+f"(d[2]), "+f"(d[3])
        : "r"(a[0]), "r"(a[1]), "r"(a[2]), "r"(a[3]), "r"(b0), "r"(b1));
}
__device__ __forceinline__ void ldsm4(uint32_t addr, uint32_t* r) {
    asm volatile("ldmatrix.sync.aligned.m8n8.x4.shared.b16 {%0,%1,%2,%3}, [%4];"
        : "=r"(r[0]), "=r"(r[1]), "=r"(r[2]), "=r"(r[3]) : "r"(addr));
}
#define CP16(dst, src) \
    asm volatile("cp.async.cg.shared.global [%0], [%1], 16;" :: "r"(dst), "l"(src))
#define CPCOMMIT() asm volatile("cp.async.commit_group;")

// ---------------------------------------------------------------------------
// x = coord @ W_node + b_node
__global__ void node_embed_kernel(const float* __restrict__ coord,
                                  const float* __restrict__ Wn,
                                  const float* __restrict__ bn) {
    int idx = blockIdx.x * blockDim.x + threadIdx.x;
    int h = idx & (H_ - 1);
    int row = idx >> 7;
    const float* c = coord + row * 3;
    d_xbuf[idx] = c[0] * Wn[h] + c[1] * Wn[H_ + h] + c[2] * Wn[2 * H_ + h] + bn[h];
}

// e = concat(ev*Wev + bev, tour*Wec0 + best*Wec1 + bec), TILED fp16
__global__ void edge_embed_kernel(const float* __restrict__ ev,
                                  const float* __restrict__ tour,
                                  const float* __restrict__ btour,
                                  const float* __restrict__ Wev,
                                  const float* __restrict__ bev,
                                  const float* __restrict__ Wec,
                                  const float* __restrict__ bec) {
    int idx4 = blockIdx.x * blockDim.x + threadIdx.x;  // uint2 units, EN_/4
    int bi = idx4 >> 13;                 // (b,i) row, 8192 uint2 each
    int local4 = idx4 & 8191;
    int block = local4 >> 4;             // 0..511 = jb*16 + hb
    int q = local4 & 15;
    int j = (block >> 4) * 8 + (q >> 1);
    int h0 = (block & 15) * 8 + (q & 1) * 4;
    int edge = bi * 256 + j;
    float4 o;
    if (h0 < H2_) {
        float v = ev[edge];
        o.x = v * Wev[h0 + 0] + bev[h0 + 0];
        o.y = v * Wev[h0 + 1] + bev[h0 + 1];
        o.z = v * Wev[h0 + 2] + bev[h0 + 2];
        o.w = v * Wev[h0 + 3] + bev[h0 + 3];
    } else {
        float t = tour[edge], bt = btour[edge];
        int g = h0 - H2_;
        o.x = t * Wec[g + 0] + bt * Wec[H2_ + g + 0] + bec[g + 0];
        o.y = t * Wec[g + 1] + bt * Wec[H2_ + g + 1] + bec[g + 1];
        o.z = t * Wec[g + 2] + bt * Wec[H2_ + g + 2] + bec[g + 2];
        o.w = t * Wec[g + 3] + bt * Wec[H2_ + g + 3] + bec[g + 3];
    }
    uint2 pk;
    pk.x = pkh2(o.x, o.y);
    pk.y = pkh2(o.z, o.w);
    reinterpret_cast<uint2*>(d_eh)[idx4] = pk;
}

// Combined per-layer prep: blocks 0-63 = Vex/Vnx/Unx gemm3 (+tiled fp16 copies);
// 64-191 = UeT fp16; block 192 = zero stats.
__global__ void __launch_bounds__(128) prep_kernel(
        const float* __restrict__ Ue,
        const float* __restrict__ Ve, const float* __restrict__ bVe,
        const float* __restrict__ Vn, const float* __restrict__ bVn,
        const float* __restrict__ Un, const float* __restrict__ bUn) {
    int bid = blockIdx.x;
    int tid = threadIdx.x;
    if (bid >= 192) {
        for (int i = tid; i < 512; i += 128) d_stats[i] = 0.f;
        return;
    }
    if (bid >= 64) {
        int h = bid - 64;
        int k = tid;
        d_UeTh[h * H_ + k] = __float2half_rn(Ue[k * H_ + h]);
        return;
    }
    __shared__ float xs[16 * H_];
    int h = tid;
    int r0 = bid * 16;
    {
        const float4* src = reinterpret_cast<const float4*>(d_xbuf + r0 * H_);
        float4* dst = reinterpret_cast<float4*>(xs);
#pragma unroll
        for (int t = 0; t < 4; ++t) dst[h + t * 128] = src[h + t * 128];
    }
    __syncthreads();
    float a0[16], a1[16], a2[16];
    {
        float v0 = bVe[h], v1 = bVn[h], v2 = bUn[h];
#pragma unroll
        for (int r = 0; r < 16; ++r) { a0[r] = v0; a1[r] = v1; a2[r] = v2; }
    }
    for (int k = 0; k < H_; k += 4) {
        float w0[4], w1[4], w2[4];
#pragma unroll
        for (int q = 0; q < 4; ++q) {
            w0[q] = Ve[(k + q) * H_ + h];
            w1[q] = Vn[(k + q) * H_ + h];
            w2[q] = Un[(k + q) * H_ + h];
        }
#pragma unroll
        for (int r = 0; r < 16; ++r) {
            float4 xv = *reinterpret_cast<const float4*>(xs + r * H_ + k);
            a0[r] += xv.x * w0[0] + xv.y * w0[1] + xv.z * w0[2] + xv.w * w0[3];
            a1[r] += xv.x * w1[0] + xv.y * w1[1] + xv.z * w1[2] + xv.w * w1[3];
            a2[r] += xv.x * w2[0] + xv.y * w2[1] + xv.z * w2[2] + xv.w * w2[3];
        }
    }
    int bb = r0 >> 8;                       // batch of this row block
    size_t pbase = (size_t)bb * 32768;      // per-b tiled plane (halves)
#pragma unroll
    for (int r = 0; r < 16; ++r) {
        int row = r0 + r;
        d_Vex[row * H_ + h] = a0[r];
        d_Unx[row * H_ + h] = a2[r];
        int j = row & 255;
        size_t off = pbase +
            (size_t)(((j >> 3) * 16 + (h >> 3)) * 64 + (j & 7) * 8 + (h & 7));
        d_VexT[off] = __float2half_rn(a0[r]);
        d_VnxT[off] = __float2half_rn(a1[r]);
    }
}

// ---------------------------------------------------------------------------
// Fused edge layer: tiled fp16 E plane, 64-j slabs double-buffered,
// warp tile 32j x 32h, ldmatrix + mma.sync, 3 CTAs/SM.
#define OFF_UH   0          // 32768 (128 rows x 256B)
#define OFF_E    32768      // 2 buffers x 16384
#define OFF_BASE 65536      // 512
#define OFF_RED  66048      // 4096
#define SMEM_F   70144

__device__ __forceinline__ void fetch_slab(uint32_t smb, size_t erow_half,
                                           int s, int tid) {
    // 1024 x 16B chunks; idx = jb(3) | kb(4) | jr(3); src tiled, dst swizzled.
#pragma unroll
    for (int t = 0; t < 4; ++t) {
        int idx = tid + t * 256;
        int jb = idx >> 7;
        int kb = (idx >> 3) & 15;
        int jr = idx & 7;
        const __half* src = d_eh + erow_half +
            (size_t)((((s * 8 + jb) * 16 + kb) * 64) + jr * 8);
        int rl = jb * 8 + jr;
        uint32_t dst = smb + OFF_E + (s & 1) * 16384 + rl * 256 +
                       ((kb ^ (rl & 7)) << 4);
        CP16(dst, src);
    }
}

__global__ void __launch_bounds__(256, 3) fused_edge_kernel(
        const float* __restrict__ bUe, int write_e) {
    extern __shared__ char smc[];
    uint32_t smb = s2u(smc);
    int tid = threadIdx.x, w = tid >> 5, lane = tid & 31;
    int wj = w & 1, wh = w >> 1;
    int bi = blockIdx.x, b = bi >> 8;
    size_t erow = (size_t)bi * (V_ * H_);   // halves

    // prologue: U tile (2048 chunks) + e slab 0
#pragma unroll
    for (int t = 0; t < 8; ++t) {
        int idx = tid + t * 256;
        int hrow = idx >> 4;
        int c = idx & 15;
        const __half* src = d_UeTh + hrow * H_ + c * 8;
        uint32_t dst = smb + OFF_UH + hrow * 256 + ((c ^ (hrow & 7)) << 4);
        CP16(dst, src);
    }
    fetch_slab(smb, erow, 0, tid);
    CPCOMMIT();
    if (tid < H_)
        reinterpret_cast<float*>(smc + OFF_BASE)[tid] =
            bUe[tid] + d_Vex[bi * H_ + tid];

    const uint32_t* VxT =
        reinterpret_cast<const uint32_t*>(d_VexT) + (size_t)b * 16384;
    const uint32_t* VnT =
        reinterpret_cast<const uint32_t*>(d_VnxT) + (size_t)b * 16384;
    uint32_t* EtT = reinterpret_cast<uint32_t*>(d_etmp) + (size_t)bi * 16384;

    // fragment addressing (smem)
    int ra = wj * 32 + (lane & 15);
    uint32_t aOff = (uint32_t)(ra * 256);
    int am = ra & 7;
    int ach = lane >> 4;
    int rb = wh * 32 + ((lane >> 4) & 1) * 8 + (lane & 7);
    uint32_t bB0 = smb + OFF_UH + rb * 256;
    uint32_t bB1 = bB0 + 16 * 256;
    int bm = rb & 7;
    int bch = (lane >> 3) & 1;

    float sN0[4], sN1[4], sD0[4], sD1[4], sS0[4], sS1[4], sQ0[4], sQ1[4];
#pragma unroll
    for (int n = 0; n < 4; ++n) {
        sN0[n] = sN1[n] = sD0[n] = sD1[n] = 0.f;
        sS0[n] = sS1[n] = sQ0[n] = sQ1[n] = 0.f;
    }

    for (int s = 0; s < 4; ++s) {
        asm volatile("cp.async.wait_group 0;");
        __syncthreads();
        if (s < 3) { fetch_slab(smb, erow, s + 1, tid); CPCOMMIT(); }

        uint32_t ebuf = smb + OFF_E + (s & 1) * 16384 + aOff;
        float acc[2][4][4];
#pragma unroll
        for (int m = 0; m < 2; ++m)
#pragma unroll
            for (int n = 0; n < 4; ++n)
#pragma unroll
                for (int q = 0; q < 4; ++q) acc[m][n][q] = 0.f;

#pragma unroll
        for (int kk = 0; kk < 8; ++kk) {
            uint32_t ah0[4], ah1[4];
            uint32_t ao = (uint32_t)(((kk * 2 + ach) ^ am) << 4);
            ldsm4(ebuf + ao, ah0);
            ldsm4(ebuf + 16 * 256 + ao, ah1);
            uint32_t bh0[4], bh1[4];
            uint32_t bo = (uint32_t)(((kk * 2 + bch) ^ bm) << 4);
            ldsm4(bB0 + bo, bh0);
            ldsm4(bB1 + bo, bh1);
            mma16816h(acc[0][0], ah0, bh0[0], bh0[1]);
            mma16816h(acc[0][1], ah0, bh0[2], bh0[3]);
            mma16816h(acc[0][2], ah0, bh1[0], bh1[1]);
            mma16816h(acc[0][3], ah0, bh1[2], bh1[3]);
            mma16816h(acc[1][0], ah1, bh0[0], bh0[1]);
            mma16816h(acc[1][1], ah1, bh0[2], bh0[3]);
            mma16816h(acc[1][2], ah1, bh1[0], bh1[1]);
            mma16816h(acc[1][3], ah1, bh1[2], bh1[3]);
        }

        // epilogue: tiled global accesses, approx-rcp sigmoids
#pragma unroll
        for (int n = 0; n < 4; ++n) {
            int h0 = wh * 32 + n * 8 + (lane & 3) * 2;
            float2 bse = *reinterpret_cast<const float2*>(smc + OFF_BASE + h0 * 4);
#pragma unroll
            for (int m = 0; m < 2; ++m) {
                int blk = (s * 8 + wj * 4 + m * 2) * 16 + (wh * 4 + n);
                float2 vx0 = up_h2(VxT[blk * 32 + lane]);
                float2 vx1 = up_h2(VxT[(blk + 16) * 32 + lane]);
                float2 vn0 = up_h2(VnT[blk * 32 + lane]);
                float2 vn1 = up_h2(VnT[(blk + 16) * 32 + lane]);
                float et00 = acc[m][n][0] + bse.x + vx0.x;
                float et01 = acc[m][n][1] + bse.y + vx0.y;
                float et10 = acc[m][n][2] + bse.x + vx1.x;
                float et11 = acc[m][n][3] + bse.y + vx1.y;
                float g00 = sigmoid_f(et00);
                float g01 = sigmoid_f(et01);
                float g10 = sigmoid_f(et10);
                float g11 = sigmoid_f(et11);
                sN0[n] += g00 * vn0.x + g10 * vn1.x;
                sN1[n] += g01 * vn0.y + g11 * vn1.y;
                sD0[n] += g00 + g10;
                sD1[n] += g01 + g11;
                if (write_e) {
                    sS0[n] += et00 + et10;
                    sS1[n] += et01 + et11;
                    sQ0[n] += et00 * et00 + et10 * et10;
                    sQ1[n] += et01 * et01 + et11 * et11;
                    EtT[blk * 32 + lane] = pkh2(et00, et01);
                    EtT[(blk + 16) * 32 + lane] = pkh2(et10, et11);
                }
            }
        }
    }

    // final reduction over j-lanes (xor shuffles), then smem across wj groups
    float* red = reinterpret_cast<float*>(smc + OFF_RED);
#pragma unroll
    for (int n = 0; n < 4; ++n) {
#pragma unroll
        for (int o = 4; o < 32; o <<= 1) {
            sN0[n] += __shfl_xor_sync(0xffffffffu, sN0[n], o);
            sN1[n] += __shfl_xor_sync(0xffffffffu, sN1[n], o);
            sD0[n] += __shfl_xor_sync(0xffffffffu, sD0[n], o);
            sD1[n] += __shfl_xor_sync(0xffffffffu, sD1[n], o);
        }
        if (write_e) {
#pragma unroll
            for (int o = 4; o < 32; o <<= 1) {
                sS0[n] += __shfl_xor_sync(0xffffffffu, sS0[n], o);
                sS1[n] += __shfl_xor_sync(0xffffffffu, sS1[n], o);
                sQ0[n] += __shfl_xor_sync(0xffffffffu, sQ0[n], o);
                sQ1[n] += __shfl_xor_sync(0xffffffffu, sQ1[n], o);
            }
        }
        if (lane < 4) {
            int h = wh * 32 + n * 8 + lane * 2;
            red[(0 * 2 + wj) * 128 + h]     = sN0[n];
            red[(0 * 2 + wj) * 128 + h + 1] = sN1[n];
            red[(1 * 2 + wj) * 128 + h]     = sD0[n];
            red[(1 * 2 + wj) * 128 + h + 1] = sD1[n];
            red[(2 * 2 + wj) * 128 + h]     = sS0[n];
            red[(2 * 2 + wj) * 128 + h + 1] = sS1[n];
            red[(3 * 2 + wj) * 128 + h]     = sQ0[n];
            red[(3 * 2 + wj) * 128 + h + 1] = sQ1[n];
        }
    }
    __syncthreads();
    if (tid < H_) {
        float n = red[tid] + red[128 + tid];
        float d = red[256 + tid] + red[384 + tid];
        float aggv = n * frcp(d + 1e-20f);
        float xt = aggv + d_Unx[bi * H_ + tid];
        d_xtmp[bi * H_ + tid] = xt;
        atomicAdd(&d_stats[256 + tid], xt);
        atomicAdd(&d_stats[384 + tid], xt * xt);
        if (write_e) {
            atomicAdd(&d_stats[tid],       red[512 + tid] + red[640 + tid]);
            atomicAdd(&d_stats[128 + tid], red[768 + tid] + red[896 + tid]);
        }
    }
}

// ---------------------------------------------------------------------------
// Merged update: blocks [0,512) x += relu(bn(x_tmp)); blocks [512,...) e-update
// in tiled fp16 layout (uint4 = 8 halves per thread = one 8h row of a block).
__global__ void update_kernel(const float* __restrict__ gx,
                              const float* __restrict__ bx,
                              const float* __restrict__ ge,
                              const float* __restrict__ be) {
    int bid = blockIdx.x;
    int tid = threadIdx.x;
    if (bid < 512) {
        int idx = bid * 256 + tid;            // XN_
        int h = idx & (H_ - 1);
        const float inv = 1.f / (float)BV_;
        float mu  = d_stats[256 + h] * inv;
        float var = d_stats[384 + h] * inv - mu * mu;
        float t = gx[h] * (d_xtmp[idx] - mu) * rsqrtf(var + 1e-5f) + bx[h];
        d_xbuf[idx] += fmaxf(t, 0.f);
        return;
    }
    int idx8 = (bid - 512) * 256 + tid;       // uint4 units, EN_/8
    int local8 = idx8 & 4095;                 // within one bi row
    int hb = (local8 >> 3) & 15;
    int h0 = hb * 8;
    const float inv = 1.f / (float)(B_ * V_ * V_);
    float sc[8], sh[8];
#pragma unroll
    for (int t2 = 0; t2 < 2; ++t2) {
        float4 s1 = *reinterpret_cast<const float4*>(d_stats + h0 + t2 * 4);
        float4 s2 = *reinterpret_cast<const float4*>(d_stats + 128 + h0 + t2 * 4);
        float4 g4 = *reinterpret_cast<const float4*>(ge + h0 + t2 * 4);
        float4 b4 = *reinterpret_cast<const float4*>(be + h0 + t2 * 4);
        float mu0 = s1.x * inv, mu1 = s1.y * inv, mu2 = s1.z * inv, mu3 = s1.w * inv;
        sc[t2*4+0] = g4.x * rsqrtf(s2.x * inv - mu0 * mu0 + 1e-5f);
        sc[t2*4+1] = g4.y * rsqrtf(s2.y * inv - mu1 * mu1 + 1e-5f);
        sc[t2*4+2] = g4.z * rsqrtf(s2.z * inv - mu2 * mu2 + 1e-5f);
        sc[t2*4+3] = g4.w * rsqrtf(s2.w * inv - mu3 * mu3 + 1e-5f);
        sh[t2*4+0] = b4.x - mu0 * sc[t2*4+0];
        sh[t2*4+1] = b4.y - mu1 * sc[t2*4+1];
        sh[t2*4+2] = b4.z - mu2 * sc[t2*4+2];
        sh[t2*4+3] = b4.w - mu3 * sc[t2*4+3];
    }
    uint4 eh = reinterpret_cast<const uint4*>(d_eh)[idx8];
    uint4 et = reinterpret_cast<const uint4*>(d_etmp)[idx8];
    uint32_t* ehp = reinterpret_cast<uint32_t*>(&eh);
    uint32_t* etp = reinterpret_cast<uint32_t*>(&et);
    uint4 outp;
    uint32_t* op = reinterpret_cast<uint32_t*>(&outp);
#pragma unroll
    for (int i = 0; i < 4; ++i) {
        float2 e2 = up_h2(ehp[i]);
        float2 t2 = up_h2(etp[i]);
        float vx = e2.x + fmaxf(t2.x * sc[i*2]   + sh[i*2],   0.f);
        float vy = e2.y + fmaxf(t2.y * sc[i*2+1] + sh[i*2+1], 0.f);
        op[i] = pkh2(vx, vy);
    }
    reinterpret_cast<uint4*>(d_eh)[idx8] = outp;
}

__global__ void zero_out_kernel(float* out) {
    if (threadIdx.x < B_) out[threadIdx.x] = 0.f;
}

// per (b,v): h = relu(x@W1+b1); v = h@W2 + b2; out[b] += v/V
__global__ void readout_kernel(const float* __restrict__ W1,
                               const float* __restrict__ b1,
                               const float* __restrict__ W2,
                               const float* __restrict__ b2,
                               float* __restrict__ out) {
    __shared__ float xs[H_];
    __shared__ float wred[4];
    int row = blockIdx.x;
    int tid = threadIdx.x;
    xs[tid] = d_xbuf[row * H_ + tid];
    __syncthreads();
    float acc = b1[tid];
#pragma unroll 8
    for (int k = 0; k < H_; ++k) acc += xs[k] * W1[k * H_ + tid];
    float v = fmaxf(acc, 0.f) * W2[tid];
#pragma unroll
    for (int o = 16; o > 0; o >>= 1) v += __shfl_down_sync(0xffffffffu, v, o);
    if ((tid & 31) == 0) wred[tid >> 5] = v;
    __syncthreads();
    if (tid == 0) {
        float s = wred[0] + wred[1] + wred[2] + wred[3] + b2[0];
        atomicAdd(&out[row >> 8], s * (1.f / (float)V_));
    }
}

// ---------------------------------------------------------------------------
extern "C" void kernel_launch(void* const* d_in, const int* in_sizes, int n_in,
                              void* d_out, int out_size) {
    const float* xev   = (const float*)d_in[1];
    const float* coord = (const float*)d_in[2];
    const float* tour  = (const float*)d_in[3];
    const float* btour = (const float*)d_in[4];
    const float* Wn    = (const float*)d_in[5];
    const float* bn    = (const float*)d_in[6];
    const float* Wev   = (const float*)d_in[7];
    const float* bev   = (const float*)d_in[8];
    const float* Wec   = (const float*)d_in[9];
    const float* bec   = (const float*)d_in[10];
    const float* Ue    = (const float*)d_in[11];
    const float* bUe   = (const float*)d_in[12];
    const float* Ve    = (const float*)d_in[13];
    const float* bVe   = (const float*)d_in[14];
    const float* Un    = (const float*)d_in[15];
    const float* bUn   = (const float*)d_in[16];
    const float* Vn    = (const float*)d_in[17];
    const float* bVn   = (const float*)d_in[18];
    const float* ge    = (const float*)d_in[19];
    const float* be    = (const float*)d_in[20];
    const float* gx    = (const float*)d_in[21];
    const float* bx    = (const float*)d_in[22];
    const float* W1    = (const float*)d_in[23];
    const float* b1    = (const float*)d_in[24];
    const float* W2    = (const float*)d_in[25];
    const float* b2    = (const float*)d_in[26];
    float* out = (float*)d_out;

    cudaFuncSetAttribute(fused_edge_kernel,
                         cudaFuncAttributeMaxDynamicSharedMemorySize, SMEM_F);

    node_embed_kernel<<<XN_ / 256, 256>>>(coord, Wn, bn);
    edge_embed_kernel<<<EN_ / 4 / 256, 256>>>(xev, tour, btour, Wev, bev, Wec, bec);

    for (int l = 0; l < L_; ++l) {
        prep_kernel<<<193, 128>>>(Ue + l * H_ * H_,
                                  Ve + l * H_ * H_, bVe + l * H_,
                                  Vn + l * H_ * H_, bVn + l * H_,
                                  Un + l * H_ * H_, bUn + l * H_);
        int write_e = (l < L_ - 1) ? 1 : 0;
        fused_edge_kernel<<<BV_, 256, SMEM_F>>>(bUe + l * H_, write_e);
        int nblk = 512 + (write_e ? (EN_ / 8 / 256) : 0);
        update_kernel<<<nblk, 256>>>(gx + l * H_, bx + l * H_,
                                     ge + l * H_, be + l * H_);
    }

    zero_out_kernel<<<1, 32>>>(out);
    readout_kernel<<<BV_, H_>>>(W1, b1, W2, b2, out);
}

// round 12
// speedup vs baseline: 1.7173x; 1.0891x over previous
#include <cuda_runtime.h>
#include <cuda_fp16.h>
#include <math.h>
#include <stdint.h>

// Problem constants
#define B_  4
#define V_  256
#define H_  128
#define H2_ 64
#define L_  3
#define BV_ (B_*V_)              // 1024
#define XN_ (BV_*H_)             // 131072
#define EN_ 33554432             // B*V*V*H

// ---------------------------------------------------------------------------
// Layouts:
//  e (d_eh): 8x8-block tiled fp16 (ldmatrix source):
//    off8(j,h) = ((j>>3)*16 + (h>>3))*64 + (j&7)*8 + (h&7)
//  Vex/Vnx/etmp: INTERLEAVED 16j x 8h blocks (128 halves = 256B). Adjacent
//  halves are the MMA fragment's j-pair (j, j+8):
//    offI(j,h) = ((j>>4)*16 + (h>>3))*128 + ((j&7)*8 + (h&7))*2 + ((j>>3)&1)
//  -> per (n,m) fragment: one uint2 per warp (index blk*32 + lane).
// ---------------------------------------------------------------------------

// Scratch (allocation-free: __device__ globals)
__device__ __align__(16) __half d_eh[EN_];     // e, 8x8 tiled fp16
__device__ __align__(16) __half d_etmp[EN_];   // e_tmp, interleaved 16x8 fp16
__device__ float d_xbuf[XN_];
__device__ float d_Vex[XN_];                   // fp32 row-major (base term)
__device__ __align__(16) __half d_VexT[XN_];   // interleaved 16x8 per-b planes
__device__ __align__(16) __half d_VnxT[XN_];
__device__ float d_Unx[XN_];
__device__ float d_xtmp[XN_];
// [0:128) e-ssum, [128:256) e-ssq, [256:384) x-sum, [384:512) x-sumsq
__device__ __align__(16) float d_stats[512];
// UeT (transposed Ue: row = output h, col = k), single fp16 plane [128][128]
__device__ __align__(16) __half d_UeTh[H_ * H_];

// ---- helpers --------------------------------------------------------------
__device__ __forceinline__ uint32_t pkh2(float a, float b) {
    __half2 t = __floats2half2_rn(a, b);
    return *reinterpret_cast<uint32_t*>(&t);
}
__device__ __forceinline__ float2 up_h2(uint32_t u) {
    __half2 t = *reinterpret_cast<__half2*>(&u);
    return make_float2(__half2float(t.x), __half2float(t.y));
}
__device__ __forceinline__ float frcp(float x) {
    float r;
    asm("rcp.approx.f32 %0, %1;" : "=f"(r) : "f"(x));
    return r;
}
__device__ __forceinline__ float sigmoid_f(float x) {
    return frcp(1.f + __expf(-x));
}
__device__ __forceinline__ uint32_t s2u(const void* p) {
    uint32_t a;
    asm("{ .reg .u64 t; cvta.to.shared.u64 t, %1; cvt.u32.u64 %0, t; }"
        : "=r"(a) : "l"(p));
    return a;
}
__device__ __forceinline__ void mma16816h(float* d, const uint32_t* a,
                                          uint32_t b0, uint32_t b1) {
    asm volatile(
        "mma.sync.aligned.m16n8k16.row.col.f32.f16.f16.f32 "
        "{%0,%1,%2,%3}, {%4,%5,%6,%7}, {%8,%9}, {%0,%1,%2,%3};"
        : "+f"(d[0]), "+f"(d[1]), "+f"(d[2]), "+f"(d[3])
        : "r"(a[0]), "r"(a[1]), "r"(a[2]), "r"(a[3]), "r"(b0), "r"(b1));
}
__device__ __forceinline__ void ldsm4(uint32_t addr, uint32_t* r) {
    asm volatile("ldmatrix.sync.aligned.m8n8.x4.shared.b16 {%0,%1,%2,%3}, [%4];"
        : "=r"(r[0]), "=r"(r[1]), "=r"(r[2]), "=r"(r[3]) : "r"(addr));
}
#define CP16(dst, src) \
    asm volatile("cp.async.cg.shared.global [%0], [%1], 16;" :: "r"(dst), "l"(src))
#define CPCOMMIT() asm volatile("cp.async.commit_group;")

// ---------------------------------------------------------------------------
// x = coord @ W_node + b_node
__global__ void node_embed_kernel(const float* __restrict__ coord,
                                  const float* __restrict__ Wn,
                                  const float* __restrict__ bn) {
    int idx = blockIdx.x * blockDim.x + threadIdx.x;
    int h = idx & (H_ - 1);
    int row = idx >> 7;
    const float* c = coord + row * 3;
    d_xbuf[idx] = c[0] * Wn[h] + c[1] * Wn[H_ + h] + c[2] * Wn[2 * H_ + h] + bn[h];
}

// e = concat(ev*Wev + bev, tour*Wec0 + best*Wec1 + bec), 8x8 TILED fp16
__global__ void edge_embed_kernel(const float* __restrict__ ev,
                                  const float* __restrict__ tour,
                                  const float* __restrict__ btour,
                                  const float* __restrict__ Wev,
                                  const float* __restrict__ bev,
                                  const float* __restrict__ Wec,
                                  const float* __restrict__ bec) {
    int idx4 = blockIdx.x * blockDim.x + threadIdx.x;  // uint2 units, EN_/4
    int bi = idx4 >> 13;                 // (b,i) row, 8192 uint2 each
    int local4 = idx4 & 8191;
    int block = local4 >> 4;             // 0..511 = jb*16 + hb
    int q = local4 & 15;
    int j = (block >> 4) * 8 + (q >> 1);
    int h0 = (block & 15) * 8 + (q & 1) * 4;
    int edge = bi * 256 + j;
    float4 o;
    if (h0 < H2_) {
        float v = ev[edge];
        o.x = v * Wev[h0 + 0] + bev[h0 + 0];
        o.y = v * Wev[h0 + 1] + bev[h0 + 1];
        o.z = v * Wev[h0 + 2] + bev[h0 + 2];
        o.w = v * Wev[h0 + 3] + bev[h0 + 3];
    } else {
        float t = tour[edge], bt = btour[edge];
        int g = h0 - H2_;
        o.x = t * Wec[g + 0] + bt * Wec[H2_ + g + 0] + bec[g + 0];
        o.y = t * Wec[g + 1] + bt * Wec[H2_ + g + 1] + bec[g + 1];
        o.z = t * Wec[g + 2] + bt * Wec[H2_ + g + 2] + bec[g + 2];
        o.w = t * Wec[g + 3] + bt * Wec[H2_ + g + 3] + bec[g + 3];
    }
    uint2 pk;
    pk.x = pkh2(o.x, o.y);
    pk.y = pkh2(o.z, o.w);
    reinterpret_cast<uint2*>(d_eh)[idx4] = pk;
}

// Combined per-layer prep: blocks 0-63 = Vex/Vnx/Unx gemm3 (+interleaved fp16);
// 64-191 = UeT fp16; block 192 = zero stats.
__global__ void __launch_bounds__(128) prep_kernel(
        const float* __restrict__ Ue,
        const float* __restrict__ Ve, const float* __restrict__ bVe,
        const float* __restrict__ Vn, const float* __restrict__ bVn,
        const float* __restrict__ Un, const float* __restrict__ bUn) {
    int bid = blockIdx.x;
    int tid = threadIdx.x;
    if (bid >= 192) {
        for (int i = tid; i < 512; i += 128) d_stats[i] = 0.f;
        return;
    }
    if (bid >= 64) {
        int h = bid - 64;
        int k = tid;
        d_UeTh[h * H_ + k] = __float2half_rn(Ue[k * H_ + h]);
        return;
    }
    __shared__ float xs[16 * H_];
    int h = tid;
    int r0 = bid * 16;
    {
        const float4* src = reinterpret_cast<const float4*>(d_xbuf + r0 * H_);
        float4* dst = reinterpret_cast<float4*>(xs);
#pragma unroll
        for (int t = 0; t < 4; ++t) dst[h + t * 128] = src[h + t * 128];
    }
    __syncthreads();
    float a0[16], a1[16], a2[16];
    {
        float v0 = bVe[h], v1 = bVn[h], v2 = bUn[h];
#pragma unroll
        for (int r = 0; r < 16; ++r) { a0[r] = v0; a1[r] = v1; a2[r] = v2; }
    }
    for (int k = 0; k < H_; k += 4) {
        float w0[4], w1[4], w2[4];
#pragma unroll
        for (int q = 0; q < 4; ++q) {
            w0[q] = Ve[(k + q) * H_ + h];
            w1[q] = Vn[(k + q) * H_ + h];
            w2[q] = Un[(k + q) * H_ + h];
        }
#pragma unroll
        for (int r = 0; r < 16; ++r) {
            float4 xv = *reinterpret_cast<const float4*>(xs + r * H_ + k);
            a0[r] += xv.x * w0[0] + xv.y * w0[1] + xv.z * w0[2] + xv.w * w0[3];
            a1[r] += xv.x * w1[0] + xv.y * w1[1] + xv.z * w1[2] + xv.w * w1[3];
            a2[r] += xv.x * w2[0] + xv.y * w2[1] + xv.z * w2[2] + xv.w * w2[3];
        }
    }
    int bb = r0 >> 8;                       // batch of this row block
    size_t pbase = (size_t)bb * 32768;      // per-b plane (halves)
#pragma unroll
    for (int r = 0; r < 16; ++r) {
        int row = r0 + r;
        d_Vex[row * H_ + h] = a0[r];
        d_Unx[row * H_ + h] = a2[r];
        int j = row & 255;
        size_t off = pbase + (size_t)(
            ((j >> 4) * 16 + (h >> 3)) * 128 +
            ((j & 7) * 8 + (h & 7)) * 2 + ((j >> 3) & 1));
        d_VexT[off] = __float2half_rn(a0[r]);
        d_VnxT[off] = __float2half_rn(a1[r]);
    }
}

// ---------------------------------------------------------------------------
// Fused edge layer: 8x8-tiled fp16 E plane, 64-j slabs double-buffered,
// warp tile 32j x 32h, ldmatrix + mma.sync, 3 CTAs/SM.
// Epilogue: interleaved layouts -> 2 LDG.64 + 1 STG.64 per fragment tile.
#define OFF_UH   0          // 32768 (128 rows x 256B)
#define OFF_E    32768      // 2 buffers x 16384
#define OFF_BASE 65536      // 512
#define OFF_RED  66048      // 4096
#define SMEM_F   70144

__device__ __forceinline__ void fetch_slab(uint32_t smb, size_t erow_half,
                                           int s, int tid) {
    // 1024 x 16B chunks; idx = jb(3) | kb(4) | jr(3); src tiled, dst swizzled.
#pragma unroll
    for (int t = 0; t < 4; ++t) {
        int idx = tid + t * 256;
        int jb = idx >> 7;
        int kb = (idx >> 3) & 15;
        int jr = idx & 7;
        const __half* src = d_eh + erow_half +
            (size_t)((((s * 8 + jb) * 16 + kb) * 64) + jr * 8);
        int rl = jb * 8 + jr;
        uint32_t dst = smb + OFF_E + (s & 1) * 16384 + rl * 256 +
                       ((kb ^ (rl & 7)) << 4);
        CP16(dst, src);
    }
}

__global__ void __launch_bounds__(256, 3) fused_edge_kernel(
        const float* __restrict__ bUe, int write_e) {
    extern __shared__ char smc[];
    uint32_t smb = s2u(smc);
    int tid = threadIdx.x, w = tid >> 5, lane = tid & 31;
    int wj = w & 1, wh = w >> 1;
    int bi = blockIdx.x, b = bi >> 8;
    size_t erow = (size_t)bi * (V_ * H_);   // halves

    // prologue: U tile (2048 chunks) + e slab 0
#pragma unroll
    for (int t = 0; t < 8; ++t) {
        int idx = tid + t * 256;
        int hrow = idx >> 4;
        int c = idx & 15;
        const __half* src = d_UeTh + hrow * H_ + c * 8;
        uint32_t dst = smb + OFF_UH + hrow * 256 + ((c ^ (hrow & 7)) << 4);
        CP16(dst, src);
    }
    fetch_slab(smb, erow, 0, tid);
    CPCOMMIT();
    if (tid < H_)
        reinterpret_cast<float*>(smc + OFF_BASE)[tid] =
            bUe[tid] + d_Vex[bi * H_ + tid];

    const uint2* VxT2 =
        reinterpret_cast<const uint2*>(d_VexT) + (size_t)b * 8192;
    const uint2* VnT2 =
        reinterpret_cast<const uint2*>(d_VnxT) + (size_t)b * 8192;
    uint2* EtT2 = reinterpret_cast<uint2*>(d_etmp) + (size_t)bi * 8192;

    // fragment addressing (smem)
    int ra = wj * 32 + (lane & 15);
    uint32_t aOff = (uint32_t)(ra * 256);
    int am = ra & 7;
    int ach = lane >> 4;
    int rb = wh * 32 + ((lane >> 4) & 1) * 8 + (lane & 7);
    uint32_t bB0 = smb + OFF_UH + rb * 256;
    uint32_t bB1 = bB0 + 16 * 256;
    int bm = rb & 7;
    int bch = (lane >> 3) & 1;

    float sN0[4], sN1[4], sD0[4], sD1[4], sS0[4], sS1[4], sQ0[4], sQ1[4];
#pragma unroll
    for (int n = 0; n < 4; ++n) {
        sN0[n] = sN1[n] = sD0[n] = sD1[n] = 0.f;
        sS0[n] = sS1[n] = sQ0[n] = sQ1[n] = 0.f;
    }

    for (int s = 0; s < 4; ++s) {
        asm volatile("cp.async.wait_group 0;");
        __syncthreads();
        if (s < 3) { fetch_slab(smb, erow, s + 1, tid); CPCOMMIT(); }

        uint32_t ebuf = smb + OFF_E + (s & 1) * 16384 + aOff;
        float acc[2][4][4];
#pragma unroll
        for (int m = 0; m < 2; ++m)
#pragma unroll
            for (int n = 0; n < 4; ++n)
#pragma unroll
                for (int q = 0; q < 4; ++q) acc[m][n][q] = 0.f;

#pragma unroll
        for (int kk = 0; kk < 8; ++kk) {
            uint32_t ah0[4], ah1[4];
            uint32_t ao = (uint32_t)(((kk * 2 + ach) ^ am) << 4);
            ldsm4(ebuf + ao, ah0);
            ldsm4(ebuf + 16 * 256 + ao, ah1);
            uint32_t bh0[4], bh1[4];
            uint32_t bo = (uint32_t)(((kk * 2 + bch) ^ bm) << 4);
            ldsm4(bB0 + bo, bh0);
            ldsm4(bB1 + bo, bh1);
            mma16816h(acc[0][0], ah0, bh0[0], bh0[1]);
            mma16816h(acc[0][1], ah0, bh0[2], bh0[3]);
            mma16816h(acc[0][2], ah0, bh1[0], bh1[1]);
            mma16816h(acc[0][3], ah0, bh1[2], bh1[3]);
            mma16816h(acc[1][0], ah1, bh0[0], bh0[1]);
            mma16816h(acc[1][1], ah1, bh0[2], bh0[3]);
            mma16816h(acc[1][2], ah1, bh1[0], bh1[1]);
            mma16816h(acc[1][3], ah1, bh1[2], bh1[3]);
        }

        // epilogue: 1 uint2 load each for Vex/Vnx, 1 uint2 store for etmp
#pragma unroll
        for (int n = 0; n < 4; ++n) {
            int h0 = wh * 32 + n * 8 + (lane & 3) * 2;
            float2 bse = *reinterpret_cast<const float2*>(smc + OFF_BASE + h0 * 4);
#pragma unroll
            for (int m = 0; m < 2; ++m) {
                int blk = (s * 4 + wj * 2 + m) * 16 + (wh * 4 + n);
                uint2 vx = VxT2[blk * 32 + lane];
                uint2 vn = VnT2[blk * 32 + lane];
                float2 vxa = up_h2(vx.x);   // (jr0,h0), (jr1,h0)
                float2 vxb = up_h2(vx.y);   // (jr0,h0+1), (jr1,h0+1)
                float2 vna = up_h2(vn.x);
                float2 vnb = up_h2(vn.y);
                float et00 = acc[m][n][0] + bse.x + vxa.x;
                float et01 = acc[m][n][1] + bse.y + vxb.x;
                float et10 = acc[m][n][2] + bse.x + vxa.y;
                float et11 = acc[m][n][3] + bse.y + vxb.y;
                float g00 = sigmoid_f(et00);
                float g01 = sigmoid_f(et01);
                float g10 = sigmoid_f(et10);
                float g11 = sigmoid_f(et11);
                sN0[n] += g00 * vna.x + g10 * vna.y;
                sN1[n] += g01 * vnb.x + g11 * vnb.y;
                sD0[n] += g00 + g10;
                sD1[n] += g01 + g11;
                if (write_e) {
                    sS0[n] += et00 + et10;
                    sS1[n] += et01 + et11;
                    sQ0[n] += et00 * et00 + et10 * et10;
                    sQ1[n] += et01 * et01 + et11 * et11;
                    EtT2[blk * 32 + lane] =
                        make_uint2(pkh2(et00, et10), pkh2(et01, et11));
                }
            }
        }
    }

    // final reduction over j-lanes (xor shuffles), then smem across wj groups
    float* red = reinterpret_cast<float*>(smc + OFF_RED);
#pragma unroll
    for (int n = 0; n < 4; ++n) {
#pragma unroll
        for (int o = 4; o < 32; o <<= 1) {
            sN0[n] += __shfl_xor_sync(0xffffffffu, sN0[n], o);
            sN1[n] += __shfl_xor_sync(0xffffffffu, sN1[n], o);
            sD0[n] += __shfl_xor_sync(0xffffffffu, sD0[n], o);
            sD1[n] += __shfl_xor_sync(0xffffffffu, sD1[n], o);
        }
        if (write_e) {
#pragma unroll
            for (int o = 4; o < 32; o <<= 1) {
                sS0[n] += __shfl_xor_sync(0xffffffffu, sS0[n], o);
                sS1[n] += __shfl_xor_sync(0xffffffffu, sS1[n], o);
                sQ0[n] += __shfl_xor_sync(0xffffffffu, sQ0[n], o);
                sQ1[n] += __shfl_xor_sync(0xffffffffu, sQ1[n], o);
            }
        }
        if (lane < 4) {
            int h = wh * 32 + n * 8 + lane * 2;
            red[(0 * 2 + wj) * 128 + h]     = sN0[n];
            red[(0 * 2 + wj) * 128 + h + 1] = sN1[n];
            red[(1 * 2 + wj) * 128 + h]     = sD0[n];
            red[(1 * 2 + wj) * 128 + h + 1] = sD1[n];
            red[(2 * 2 + wj) * 128 + h]     = sS0[n];
            red[(2 * 2 + wj) * 128 + h + 1] = sS1[n];
            red[(3 * 2 + wj) * 128 + h]     = sQ0[n];
            red[(3 * 2 + wj) * 128 + h + 1] = sQ1[n];
        }
    }
    __syncthreads();
    if (tid < H_) {
        float n = red[tid] + red[128 + tid];
        float d = red[256 + tid] + red[384 + tid];
        float aggv = n * frcp(d + 1e-20f);
        float xt = aggv + d_Unx[bi * H_ + tid];
        d_xtmp[bi * H_ + tid] = xt;
        atomicAdd(&d_stats[256 + tid], xt);
        atomicAdd(&d_stats[384 + tid], xt * xt);
        if (write_e) {
            atomicAdd(&d_stats[tid],       red[512 + tid] + red[640 + tid]);
            atomicAdd(&d_stats[128 + tid], red[768 + tid] + red[896 + tid]);
        }
    }
}

// ---------------------------------------------------------------------------
// Merged update: blocks [0,512) x += relu(bn(x_tmp)); blocks [512,...) e-update
// (etmp interleaved 16x8 -> eh 8x8 translation; coalesced on both sides).
__global__ void update_kernel(const float* __restrict__ gx,
                              const float* __restrict__ bx,
                              const float* __restrict__ ge,
                              const float* __restrict__ be) {
    int bid = blockIdx.x;
    int tid = threadIdx.x;
    if (bid < 512) {
        int idx = bid * 256 + tid;            // XN_
        int h = idx & (H_ - 1);
        const float inv = 1.f / (float)BV_;
        float mu  = d_stats[256 + h] * inv;
        float var = d_stats[384 + h] * inv - mu * mu;
        float t = gx[h] * (d_xtmp[idx] - mu) * rsqrtf(var + 1e-5f) + bx[h];
        d_xbuf[idx] += fmaxf(t, 0.f);
        return;
    }
    int idx8 = (bid - 512) * 256 + tid;       // uint4 units, EN_/8
    int bi = idx8 >> 12;                       // 4096 uint4 per (b,i) row
    int local8 = idx8 & 4095;
    int block = local8 >> 4;                   // interleaved block index
    int q = local8 & 15;
    int jb2 = block >> 4, hb = block & 15;
    int r = q >> 1, hq4 = (q & 1) * 4;
    int h0 = hb * 8 + hq4;                     // 4 consecutive h
    const float inv = 1.f / (float)(B_ * V_ * V_);
    float4 s1 = *reinterpret_cast<const float4*>(d_stats + h0);
    float4 s2 = *reinterpret_cast<const float4*>(d_stats + 128 + h0);
    float4 g4 = *reinterpret_cast<const float4*>(ge + h0);
    float4 b4 = *reinterpret_cast<const float4*>(be + h0);
    float mu0 = s1.x * inv, mu1 = s1.y * inv, mu2 = s1.z * inv, mu3 = s1.w * inv;
    float sc0 = g4.x * rsqrtf(s2.x * inv - mu0 * mu0 + 1e-5f);
    float sc1 = g4.y * rsqrtf(s2.y * inv - mu1 * mu1 + 1e-5f);
    float sc2 = g4.z * rsqrtf(s2.z * inv - mu2 * mu2 + 1e-5f);
    float sc3 = g4.w * rsqrtf(s2.w * inv - mu3 * mu3 + 1e-5f);
    float sh0 = b4.x - mu0 * sc0, sh1 = b4.y - mu1 * sc1;
    float sh2 = b4.z - mu2 * sc2, sh3 = b4.w - mu3 * sc3;

    uint4 et = reinterpret_cast<const uint4*>(d_etmp)[idx8];
    size_t ehbase = (size_t)bi * 32768;        // halves per row
    uint32_t offA = (uint32_t)(((jb2 * 2) * 16 + hb) * 64 + r * 8 + hq4);
    uint32_t offB = offA + 1024;               // j+8 block row
    uint2 eA = *reinterpret_cast<const uint2*>(d_eh + ehbase + offA);
    uint2 eB = *reinterpret_cast<const uint2*>(d_eh + ehbase + offB);
    float2 ea01 = up_h2(eA.x), ea23 = up_h2(eA.y);
    float2 eb01 = up_h2(eB.x), eb23 = up_h2(eB.y);
    float2 t0 = up_h2(et.x);   // (j0, j1) at h0
    float2 t1 = up_h2(et.y);   // h0+1
    float2 t2 = up_h2(et.z);   // h0+2
    float2 t3 = up_h2(et.w);   // h0+3
    float a0 = ea01.x + fmaxf(t0.x * sc0 + sh0, 0.f);
    float a1 = ea01.y + fmaxf(t1.x * sc1 + sh1, 0.f);
    float a2 = ea23.x + fmaxf(t2.x * sc2 + sh2, 0.f);
    float a3 = ea23.y + fmaxf(t3.x * sc3 + sh3, 0.f);
    float c0 = eb01.x + fmaxf(t0.y * sc0 + sh0, 0.f);
    float c1 = eb01.y + fmaxf(t1.y * sc1 + sh1, 0.f);
    float c2 = eb23.x + fmaxf(t2.y * sc2 + sh2, 0.f);
    float c3 = eb23.y + fmaxf(t3.y * sc3 + sh3, 0.f);
    uint2 oA = make_uint2(pkh2(a0, a1), pkh2(a2, a3));
    uint2 oB = make_uint2(pkh2(c0, c1), pkh2(c2, c3));
    *reinterpret_cast<uint2*>(d_eh + ehbase + offA) = oA;
    *reinterpret_cast<uint2*>(d_eh + ehbase + offB) = oB;
}

__global__ void zero_out_kernel(float* out) {
    if (threadIdx.x < B_) out[threadIdx.x] = 0.f;
}

// per (b,v): h = relu(x@W1+b1); v = h@W2 + b2; out[b] += v/V
__global__ void readout_kernel(const float* __restrict__ W1,
                               const float* __restrict__ b1,
                               const float* __restrict__ W2,
                               const float* __restrict__ b2,
                               float* __restrict__ out) {
    __shared__ float xs[H_];
    __shared__ float wred[4];
    int row = blockIdx.x;
    int tid = threadIdx.x;
    xs[tid] = d_xbuf[row * H_ + tid];
    __syncthreads();
    float acc = b1[tid];
#pragma unroll 8
    for (int k = 0; k < H_; ++k) acc += xs[k] * W1[k * H_ + tid];
    float v = fmaxf(acc, 0.f) * W2[tid];
#pragma unroll
    for (int o = 16; o > 0; o >>= 1) v += __shfl_down_sync(0xffffffffu, v, o);
    if ((tid & 31) == 0) wred[tid >> 5] = v;
    __syncthreads();
    if (tid == 0) {
        float s = wred[0] + wred[1] + wred[2] + wred[3] + b2[0];
        atomicAdd(&out[row >> 8], s * (1.f / (float)V_));
    }
}

// ---------------------------------------------------------------------------
extern "C" void kernel_launch(void* const* d_in, const int* in_sizes, int n_in,
                              void* d_out, int out_size) {
    const float* xev   = (const float*)d_in[1];
    const float* coord = (const float*)d_in[2];
    const float* tour  = (const float*)d_in[3];
    const float* btour = (const float*)d_in[4];
    const float* Wn    = (const float*)d_in[5];
    const float* bn    = (const float*)d_in[6];
    const float* Wev   = (const float*)d_in[7];
    const float* bev   = (const float*)d_in[8];
    const float* Wec   = (const float*)d_in[9];
    const float* bec   = (const float*)d_in[10];
    const float* Ue    = (const float*)d_in[11];
    const float* bUe   = (const float*)d_in[12];
    const float* Ve    = (const float*)d_in[13];
    const float* bVe   = (const float*)d_in[14];
    const float* Un    = (const float*)d_in[15];
    const float* bUn   = (const float*)d_in[16];
    const float* Vn    = (const float*)d_in[17];
    const float* bVn   = (const float*)d_in[18];
    const float* ge    = (const float*)d_in[19];
    const float* be    = (const float*)d_in[20];
    const float* gx    = (const float*)d_in[21];
    const float* bx    = (const float*)d_in[22];
    const float* W1    = (const float*)d_in[23];
    const float* b1    = (const float*)d_in[24];
    const float* W2    = (const float*)d_in[25];
    const float* b2    = (const float*)d_in[26];
    float* out = (float*)d_out;

    cudaFuncSetAttribute(fused_edge_kernel,
                         cudaFuncAttributeMaxDynamicSharedMemorySize, SMEM_F);

    node_embed_kernel<<<XN_ / 256, 256>>>(coord, Wn, bn);
    edge_embed_kernel<<<EN_ / 4 / 256, 256>>>(xev, tour, btour, Wev, bev, Wec, bec);

    for (int l = 0; l < L_; ++l) {
        prep_kernel<<<193, 128>>>(Ue + l * H_ * H_,
                                  Ve + l * H_ * H_, bVe + l * H_,
                                  Vn + l * H_ * H_, bVn + l * H_,
                                  Un + l * H_ * H_, bUn + l * H_);
        int write_e = (l < L_ - 1) ? 1 : 0;
        fused_edge_kernel<<<BV_, 256, SMEM_F>>>(bUe + l * H_, write_e);
        int nblk = 512 + (write_e ? (EN_ / 8 / 256) : 0);
        update_kernel<<<nblk, 256>>>(gx + l * H_, bx + l * H_,
                                     ge + l * H_, be + l * H_);
    }

    zero_out_kernel<<<1, 32>>>(out);
    readout_kernel<<<BV_, H_>>>(W1, b1, W2, b2, out);
}